// round 11
// baseline (speedup 1.0000x reference)
#include <cuda_runtime.h>
#include <cuda_bf16.h>
#include <math.h>
#include <stdint.h>

#define BB 8
#define SS 2048
#define DD 1024
#define HH 64

// Scratch.
__device__ float g_Q[BB * SS * HH];                 // fp32 Q
__device__ float g_V[BB * SS * HH];                 // fp32 V (input to prep_vt)
__device__ uint32_t g_Khp[BB * SS * 32];            // K hi, bf16x2 pairs along h
__device__ uint32_t g_Klp[BB * SS * 32];            // K lo
__device__ uint32_t g_Vthp[BB * 64 * 1024];         // V^T hi: [b][h][s/2] pairs along s
__device__ uint32_t g_Vtlp[BB * 64 * 1024];         // V^T lo
__device__ __nv_bfloat16 g_Bh[192 * 1024];          // weights hi  [n][k]
__device__ __nv_bfloat16 g_Bl[192 * 1024];          // weights lo

// Split-K partials: unit = (b, qb, ci) -> 64x64 unnormalized O + per-row m,l.
__device__ float g_pO[BB * 32 * 4 * 64 * 64];       // 16.8 MB
__device__ float g_pm[BB * 32 * 4 * 64];
__device__ float g_pl[BB * 32 * 4 * 64];

// ---------------------------------------------------------------------------
__device__ __forceinline__ void tsplit2(float a, float b, uint32_t& hi, uint32_t& lo) {
    uint32_t ia = __float_as_uint(a), ib = __float_as_uint(b);
    hi = __byte_perm(ia, ib, 0x7632);
    float ra = a - __uint_as_float(ia & 0xFFFF0000u);
    float rb = b - __uint_as_float(ib & 0xFFFF0000u);
    asm("cvt.rn.bf16x2.f32 %0, %1, %2;" : "=r"(lo) : "f"(rb), "f"(ra));
}

__device__ __forceinline__ float exp2_fast(float x) {
    x = fmaxf(x, -80.0f);
    float z = x + 12582912.0f;
    float n = z - 12582912.0f;
    float f = x - n;
    float p =            1.3333558e-3f;
    p = fmaf(p, f, 9.6181291e-3f);
    p = fmaf(p, f, 5.5504109e-2f);
    p = fmaf(p, f, 2.4022650e-1f);
    p = fmaf(p, f, 6.9314718e-1f);
    p = fmaf(p, f, 1.0f);
    int e = __float_as_int(z);
    float sc = __int_as_float((e + (127 - 0x4B400000)) << 23);
    return p * sc;
}

__device__ __forceinline__ void mma_bf16(float c[4],
                                         uint32_t a0, uint32_t a1, uint32_t a2, uint32_t a3,
                                         uint32_t b0, uint32_t b1) {
    asm volatile(
        "mma.sync.aligned.m16n8k16.row.col.f32.bf16.bf16.f32 "
        "{%0,%1,%2,%3}, {%4,%5,%6,%7}, {%8,%9}, {%0,%1,%2,%3};"
        : "+f"(c[0]), "+f"(c[1]), "+f"(c[2]), "+f"(c[3])
        : "r"(a0), "r"(a1), "r"(a2), "r"(a3), "r"(b0), "r"(b1));
}

__device__ __forceinline__ uint32_t lds32(const __nv_bfloat16* p) {
    return *(const uint32_t*)p;
}

// ---------------------------------------------------------------------------
// Kernel 0: split weights.
// ---------------------------------------------------------------------------
__global__ void prep_w(const float* __restrict__ Wq,
                       const float* __restrict__ Wk,
                       const float* __restrict__ Wv)
{
    int i = blockIdx.x * blockDim.x + threadIdx.x;
    int n = i >> 10;
    int k = i & 1023;
    int m = n >> 6;
    int col = n & 63;
    const float* W = (m == 0) ? Wq : (m == 1) ? Wk : Wv;
    float w = W[k * 64 + col];
    __nv_bfloat16 h = __float2bfloat16(w);
    float lo = w - __bfloat162float(h);
    g_Bh[(size_t)n * 1024 + k] = h;
    g_Bl[(size_t)n * 1024 + k] = __float2bfloat16(lo);
}

// ---------------------------------------------------------------------------
// Kernel 1: QKV projection. M=128 tile, 512 threads (16 warps) for latency
// hiding: warp grid 4(M) x 4(N), warp tile 32 x 48 = 2 mt x 6 nt.
// B traffic per CTA unchanged vs 256-thr version; warps/SMSP 2 -> 4.
// ---------------------------------------------------------------------------
#define APITCH 36
#define BPITCH 36

__global__ __launch_bounds__(512) void qkv_mma(const float* __restrict__ x)
{
    __shared__ __align__(16) __nv_bfloat16 Ah[128 * APITCH];
    __shared__ __align__(16) __nv_bfloat16 Al[128 * APITCH];
    __shared__ __align__(16) __nv_bfloat16 Bh[192 * BPITCH];
    __shared__ __align__(16) __nv_bfloat16 Bl[192 * BPITCH];

    const int tid = threadIdx.x;
    const int wid = tid >> 5;
    const int lane = tid & 31;
    const int grow = lane >> 2;
    const int tg = lane & 3;
    const int warp_m = wid & 3;      // 32 rows
    const int warp_n = wid >> 2;     // 48 cols
    const int row0 = blockIdx.x * 128;

    float acc[2][6][4] = {};

    for (int k0 = 0; k0 < DD; k0 += 32) {
        // ---- A: x fp32 [128 x 32] -> hi/lo bf16 (2 float4 per thread).
        #pragma unroll
        for (int i = 0; i < 2; i++) {
            int idx = tid + (i << 9);        // 0..1023
            int r = idx >> 3;
            int c4 = idx & 7;
            float4 f = *(const float4*)(x + (size_t)(row0 + r) * DD + k0 + c4 * 4);
            uint32_t h01, l01, h23, l23;
            tsplit2(f.x, f.y, h01, l01);
            tsplit2(f.z, f.w, h23, l23);
            int off = r * APITCH + c4 * 4;
            *(uint2*)&Ah[off] = make_uint2(h01, h23);
            *(uint2*)&Al[off] = make_uint2(l01, l23);
        }
        // ---- B: [192 x 32] bf16 hi/lo = 768 uint4 slots per array.
        {
            int idx = tid;                   // slots tid and tid+512 (if < 768)
            #pragma unroll
            for (int i = 0; i < 2; i++) {
                if (idx < 768) {
                    int r = idx >> 2;
                    int q = idx & 3;
                    int off = r * BPITCH + q * 8;
                    uint4 vh = *(const uint4*)(g_Bh + (size_t)r * 1024 + k0 + q * 8);
                    uint4 vl = *(const uint4*)(g_Bl + (size_t)r * 1024 + k0 + q * 8);
                    *(uint2*)&Bh[off]     = make_uint2(vh.x, vh.y);
                    *(uint2*)&Bh[off + 4] = make_uint2(vh.z, vh.w);
                    *(uint2*)&Bl[off]     = make_uint2(vl.x, vl.y);
                    *(uint2*)&Bl[off + 4] = make_uint2(vl.z, vl.w);
                }
                idx += 512;
            }
        }
        __syncthreads();

        #pragma unroll
        for (int ks = 0; ks < 2; ks++) {
            const int kofs = ks * 16 + tg * 2;
            uint32_t ah[2][4], al[2][4];
            #pragma unroll
            for (int mt = 0; mt < 2; mt++) {
                int rb = (warp_m * 32 + mt * 16 + grow) * APITCH + kofs;
                ah[mt][0] = lds32(Ah + rb);
                ah[mt][1] = lds32(Ah + rb + 8 * APITCH);
                ah[mt][2] = lds32(Ah + rb + 8);
                ah[mt][3] = lds32(Ah + rb + 8 * APITCH + 8);
                al[mt][0] = lds32(Al + rb);
                al[mt][1] = lds32(Al + rb + 8 * APITCH);
                al[mt][2] = lds32(Al + rb + 8);
                al[mt][3] = lds32(Al + rb + 8 * APITCH + 8);
            }
            #pragma unroll
            for (int nt = 0; nt < 6; nt++) {
                int cb = (warp_n * 48 + nt * 8 + grow) * BPITCH + kofs;
                uint32_t bh0 = lds32(Bh + cb);
                uint32_t bh1 = lds32(Bh + cb + 8);
                uint32_t bl0 = lds32(Bl + cb);
                uint32_t bl1 = lds32(Bl + cb + 8);
                #pragma unroll
                for (int mt = 0; mt < 2; mt++) {
                    mma_bf16(acc[mt][nt], ah[mt][0], ah[mt][1], ah[mt][2], ah[mt][3], bh0, bh1);
                    mma_bf16(acc[mt][nt], ah[mt][0], ah[mt][1], ah[mt][2], ah[mt][3], bl0, bl1);
                    mma_bf16(acc[mt][nt], al[mt][0], al[mt][1], al[mt][2], al[mt][3], bh0, bh1);
                }
            }
        }
        __syncthreads();
    }

    // Epilogue: Q,V fp32; K split once into bf16 hi/lo pair arrays.
    #pragma unroll
    for (int mt = 0; mt < 2; mt++) {
        int r = row0 + warp_m * 32 + mt * 16 + grow;
        #pragma unroll
        for (int nt = 0; nt < 6; nt++) {
            int col = warp_n * 48 + nt * 8 + tg * 2;
            int mat = col >> 6;
            int c = col & 63;
            if (mat == 1) {
                uint32_t h0, l0, h1, l1;
                tsplit2(acc[mt][nt][0], acc[mt][nt][1], h0, l0);
                tsplit2(acc[mt][nt][2], acc[mt][nt][3], h1, l1);
                int pidx = c >> 1;
                g_Khp[(size_t)r * 32 + pidx] = h0;
                g_Klp[(size_t)r * 32 + pidx] = l0;
                g_Khp[(size_t)(r + 8) * 32 + pidx] = h1;
                g_Klp[(size_t)(r + 8) * 32 + pidx] = l1;
            } else {
                float* dst = (mat == 0) ? g_Q : g_V;
                *(float2*)(dst + (size_t)r * 64 + c) =
                    make_float2(acc[mt][nt][0], acc[mt][nt][1]);
                *(float2*)(dst + (size_t)(r + 8) * 64 + c) =
                    make_float2(acc[mt][nt][2], acc[mt][nt][3]);
            }
        }
    }
}

// ---------------------------------------------------------------------------
// Kernel 1b: transpose + split V once.
// ---------------------------------------------------------------------------
__global__ __launch_bounds__(256) void prep_vt()
{
    __shared__ float vt[64 * 65];
    const int tid = threadIdx.x;
    const int s0 = blockIdx.x * 64;
    const int b  = blockIdx.y;

    #pragma unroll
    for (int i = 0; i < 4; i++) {
        int idx = tid + (i << 8);
        int r = idx >> 4;
        int c4 = (idx & 15) << 2;
        float4 f = *(const float4*)(g_V + (size_t)(b * SS + s0 + r) * 64 + c4);
        vt[r * 65 + c4 + 0] = f.x;  vt[r * 65 + c4 + 1] = f.y;
        vt[r * 65 + c4 + 2] = f.z;  vt[r * 65 + c4 + 3] = f.w;
    }
    __syncthreads();

    #pragma unroll
    for (int i = 0; i < 8; i++) {
        int idx = tid + (i << 8);
        int h  = idx >> 5;
        int sp = idx & 31;
        float v0 = vt[(sp * 2 + 0) * 65 + h];
        float v1 = vt[(sp * 2 + 1) * 65 + h];
        uint32_t hi, lo;
        tsplit2(v0, v1, hi, lo);
        size_t o = (size_t)(b * 64 + h) * 1024 + (s0 >> 1) + sp;
        g_Vthp[o] = hi;
        g_Vtlp[o] = lo;
    }
}

// ---------------------------------------------------------------------------
// Kernel 2a: split-K flash attention partials (R10 version + 3 CTAs/SM pin).
// ---------------------------------------------------------------------------
#define KPITCH 72
#define SCL 0.18033688011112042f   /* 0.125 * log2(e) */

__global__ __launch_bounds__(128, 3) void attn_part(float* __restrict__ dummy)
{
    __shared__ __align__(16) __nv_bfloat16 Kh[64 * KPITCH];
    __shared__ __align__(16) __nv_bfloat16 Kl[64 * KPITCH];
    __shared__ __align__(16) __nv_bfloat16 Vth[64 * KPITCH];
    __shared__ __align__(16) __nv_bfloat16 Vtl[64 * KPITCH];
    (void)dummy;

    const int tid = threadIdx.x;
    const int wm = tid >> 5;
    const int lane = tid & 31;
    const int grow = lane >> 2;
    const int tg = lane & 3;
    const int u = blockIdx.x;          // 0..79
    const int b = blockIdx.y;

    int qb, ci;
    if (u < 8)       { qb = u;                 ci = 0; }
    else if (u < 24) { qb = 8  + ((u - 8) >> 1);  ci = (u - 8) & 1; }
    else if (u < 48) { qb = 16 + (u - 24) / 3;    ci = (u - 24) % 3; }
    else             { qb = 24 + ((u - 48) >> 2); ci = (u - 48) & 3; }

    const int kb0 = ci * 8;
    const int kb1 = min(kb0 + 7, qb);

    const float* Qg = g_Q + (size_t)(b * SS + qb * 64 + wm * 16) * HH;

    uint32_t qh[4][4], ql[4][4];
    #pragma unroll
    for (int kt = 0; kt < 4; kt++) {
        float2 v00 = *(const float2*)(Qg + grow * HH + kt * 16 + tg * 2);
        float2 v10 = *(const float2*)(Qg + (grow + 8) * HH + kt * 16 + tg * 2);
        float2 v01 = *(const float2*)(Qg + grow * HH + kt * 16 + tg * 2 + 8);
        float2 v11 = *(const float2*)(Qg + (grow + 8) * HH + kt * 16 + tg * 2 + 8);
        tsplit2(v00.x, v00.y, qh[kt][0], ql[kt][0]);
        tsplit2(v10.x, v10.y, qh[kt][1], ql[kt][1]);
        tsplit2(v01.x, v01.y, qh[kt][2], ql[kt][2]);
        tsplit2(v11.x, v11.y, qh[kt][3], ql[kt][3]);
    }

    float o[8][4] = {};
    float m0 = -1e30f, m1 = -1e30f, l0 = 0.0f, l1 = 0.0f;
    const int qr0 = qb * 64 + wm * 16 + grow;

    const uint4* Khg4 = (const uint4*)(g_Khp + (size_t)b * SS * 32);
    const uint4* Klg4 = (const uint4*)(g_Klp + (size_t)b * SS * 32);
    const uint4* Vhg4 = (const uint4*)(g_Vthp + (size_t)b * 64 * 1024);
    const uint4* Vlg4 = (const uint4*)(g_Vtlp + (size_t)b * 64 * 1024);

    for (int kb = kb0; kb <= kb1; kb++) {
        #pragma unroll
        for (int i = 0; i < 4; i++) {
            int idx = tid + (i << 7);    // 0..511
            int r = idx >> 3, q = idx & 7;
            *(uint4*)&Kh[r * KPITCH + q * 8]  = Khg4[(size_t)(kb * 64 + r) * 8 + q];
            *(uint4*)&Kl[r * KPITCH + q * 8]  = Klg4[(size_t)(kb * 64 + r) * 8 + q];
            *(uint4*)&Vth[r * KPITCH + q * 8] = Vhg4[(size_t)r * 256 + kb * 8 + q];
            *(uint4*)&Vtl[r * KPITCH + q * 8] = Vlg4[(size_t)r * 256 + kb * 8 + q];
        }
        __syncthreads();

        float s[8][4] = {};
        #pragma unroll
        for (int nt = 0; nt < 8; nt++) {
            #pragma unroll
            for (int kt = 0; kt < 4; kt++) {
                int cb = (nt * 8 + grow) * KPITCH + kt * 16 + tg * 2;
                uint32_t bh0 = lds32(Kh + cb), bh1 = lds32(Kh + cb + 8);
                uint32_t bl0 = lds32(Kl + cb), bl1 = lds32(Kl + cb + 8);
                mma_bf16(s[nt], qh[kt][0], qh[kt][1], qh[kt][2], qh[kt][3], bh0, bh1);
                mma_bf16(s[nt], qh[kt][0], qh[kt][1], qh[kt][2], qh[kt][3], bl0, bl1);
                mma_bf16(s[nt], ql[kt][0], ql[kt][1], ql[kt][2], ql[kt][3], bh0, bh1);
            }
        }

        if (kb == qb) {
            #pragma unroll
            for (int nt = 0; nt < 8; nt++) {
                int kc = kb * 64 + nt * 8 + tg * 2;
                s[nt][0] = (kc     > qr0)     ? -1e30f : s[nt][0] * SCL;
                s[nt][1] = (kc + 1 > qr0)     ? -1e30f : s[nt][1] * SCL;
                s[nt][2] = (kc     > qr0 + 8) ? -1e30f : s[nt][2] * SCL;
                s[nt][3] = (kc + 1 > qr0 + 8) ? -1e30f : s[nt][3] * SCL;
            }
        } else {
            #pragma unroll
            for (int nt = 0; nt < 8; nt++) {
                s[nt][0] *= SCL; s[nt][1] *= SCL;
                s[nt][2] *= SCL; s[nt][3] *= SCL;
            }
        }

        float mx0 = -1e30f, mx1 = -1e30f;
        #pragma unroll
        for (int nt = 0; nt < 8; nt++) {
            mx0 = fmaxf(mx0, fmaxf(s[nt][0], s[nt][1]));
            mx1 = fmaxf(mx1, fmaxf(s[nt][2], s[nt][3]));
        }
        mx0 = fmaxf(mx0, __shfl_xor_sync(0xffffffffu, mx0, 1));
        mx0 = fmaxf(mx0, __shfl_xor_sync(0xffffffffu, mx0, 2));
        mx1 = fmaxf(mx1, __shfl_xor_sync(0xffffffffu, mx1, 1));
        mx1 = fmaxf(mx1, __shfl_xor_sync(0xffffffffu, mx1, 2));
        float nm0 = fmaxf(m0, mx0), nm1 = fmaxf(m1, mx1);
        float a0 = exp2_fast(m0 - nm0), a1 = exp2_fast(m1 - nm1);
        m0 = nm0; m1 = nm1;

        float rs0 = 0.0f, rs1 = 0.0f;
        #pragma unroll
        for (int nt = 0; nt < 8; nt++) {
            float p0 = exp2_fast(s[nt][0] - nm0);
            float p1 = exp2_fast(s[nt][1] - nm0);
            float p2 = exp2_fast(s[nt][2] - nm1);
            float p3 = exp2_fast(s[nt][3] - nm1);
            s[nt][0] = p0; s[nt][1] = p1; s[nt][2] = p2; s[nt][3] = p3;
            rs0 += p0 + p1;
            rs1 += p2 + p3;
        }
        rs0 += __shfl_xor_sync(0xffffffffu, rs0, 1);
        rs0 += __shfl_xor_sync(0xffffffffu, rs0, 2);
        rs1 += __shfl_xor_sync(0xffffffffu, rs1, 1);
        rs1 += __shfl_xor_sync(0xffffffffu, rs1, 2);
        l0 = l0 * a0 + rs0;
        l1 = l1 * a1 + rs1;
        #pragma unroll
        for (int nt = 0; nt < 8; nt++) {
            o[nt][0] *= a0; o[nt][1] *= a0;
            o[nt][2] *= a1; o[nt][3] *= a1;
        }

        #pragma unroll
        for (int kt = 0; kt < 4; kt++) {
            uint32_t ph[4], pl[4];
            tsplit2(s[2 * kt][0],     s[2 * kt][1],     ph[0], pl[0]);
            tsplit2(s[2 * kt][2],     s[2 * kt][3],     ph[1], pl[1]);
            tsplit2(s[2 * kt + 1][0], s[2 * kt + 1][1], ph[2], pl[2]);
            tsplit2(s[2 * kt + 1][2], s[2 * kt + 1][3], ph[3], pl[3]);
            #pragma unroll
            for (int nt = 0; nt < 8; nt++) {
                int cb = (nt * 8 + grow) * KPITCH + kt * 16 + tg * 2;
                uint32_t bh0 = lds32(Vth + cb), bh1 = lds32(Vth + cb + 8);
                uint32_t bl0 = lds32(Vtl + cb), bl1 = lds32(Vtl + cb + 8);
                mma_bf16(o[nt], ph[0], ph[1], ph[2], ph[3], bh0, bh1);
                mma_bf16(o[nt], ph[0], ph[1], ph[2], ph[3], bl0, bl1);
                mma_bf16(o[nt], pl[0], pl[1], pl[2], pl[3], bh0, bh1);
            }
        }
        __syncthreads();
    }

    const size_t unit = ((size_t)b * 32 + qb) * 4 + ci;
    float* pO = g_pO + unit * 4096 + (size_t)(wm * 16) * 64;
    #pragma unroll
    for (int nt = 0; nt < 8; nt++) {
        *(float2*)(pO + grow * 64 + nt * 8 + tg * 2) = make_float2(o[nt][0], o[nt][1]);
        *(float2*)(pO + (grow + 8) * 64 + nt * 8 + tg * 2) = make_float2(o[nt][2], o[nt][3]);
    }
    if (tg == 0) {
        g_pm[unit * 64 + wm * 16 + grow]     = m0;
        g_pm[unit * 64 + wm * 16 + grow + 8] = m1;
        g_pl[unit * 64 + wm * 16 + grow]     = l0;
        g_pl[unit * 64 + wm * 16 + grow + 8] = l1;
    }
}

// ---------------------------------------------------------------------------
// Kernel 2b: combine partials. Grid (32, 8), 256 threads.
// ---------------------------------------------------------------------------
__global__ __launch_bounds__(256) void attn_combine(float* __restrict__ Out)
{
    const int qb = blockIdx.x;
    const int b  = blockIdx.y;
    const int tid = threadIdx.x;
    const int r = tid >> 2;
    const int c0 = (tid & 3) * 16;
    const int nc = (qb >> 3) + 1;

    const size_t ubase = ((size_t)b * 32 + qb) * 4;

    float mi[4], li[4];
    float M = -1e30f;
    #pragma unroll 4
    for (int i = 0; i < nc; i++) {
        mi[i] = g_pm[(ubase + i) * 64 + r];
        li[i] = g_pl[(ubase + i) * 64 + r];
        M = fmaxf(M, mi[i]);
    }

    float acc[16] = {};
    float L = 0.0f;
    #pragma unroll 4
    for (int i = 0; i < nc; i++) {
        float al = exp2_fast(mi[i] - M);
        L += al * li[i];
        const float* pO = g_pO + (ubase + i) * 4096 + (size_t)r * 64 + c0;
        #pragma unroll
        for (int q = 0; q < 4; q++) {
            float4 v = *(const float4*)(pO + q * 4);
            acc[q * 4 + 0] += al * v.x;
            acc[q * 4 + 1] += al * v.y;
            acc[q * 4 + 2] += al * v.z;
            acc[q * 4 + 3] += al * v.w;
        }
    }

    float inv = 1.0f / L;
    float* Og = Out + (size_t)(b * SS + qb * 64 + r) * HH + c0;
    #pragma unroll
    for (int q = 0; q < 4; q++) {
        *(float4*)(Og + q * 4) = make_float4(acc[q * 4 + 0] * inv, acc[q * 4 + 1] * inv,
                                             acc[q * 4 + 2] * inv, acc[q * 4 + 3] * inv);
    }
}

// ---------------------------------------------------------------------------
extern "C" void kernel_launch(void* const* d_in, const int* in_sizes, int n_in,
                              void* d_out, int out_size)
{
    const float* x  = (const float*)d_in[0];
    const float* Wq = (const float*)d_in[1];
    const float* Wk = (const float*)d_in[2];
    const float* Wv = (const float*)d_in[3];
    float* out = (float*)d_out;
    (void)in_sizes; (void)n_in; (void)out_size;

    prep_w<<<768, 256>>>(Wq, Wk, Wv);
    qkv_mma<<<(BB * SS) / 128, 512>>>(x);
    prep_vt<<<dim3(SS / 64, BB), 256>>>();
    attn_part<<<dim3(80, BB), 128>>>(out);
    attn_combine<<<dim3(32, BB), 256>>>(out);
}

// round 12
// speedup vs baseline: 1.0494x; 1.0494x over previous
#include <cuda_runtime.h>
#include <cuda_bf16.h>
#include <math.h>
#include <stdint.h>

#define BB 8
#define SS 2048
#define DD 1024
#define HH 64

// Scratch.
__device__ float g_Q[BB * SS * HH];                 // fp32 Q
__device__ uint32_t g_Khp[BB * SS * 32];            // K hi, bf16x2 pairs along h
__device__ uint32_t g_Klp[BB * SS * 32];            // K lo
__device__ uint32_t g_Vthp[BB * 64 * 1024];         // V^T hi: [b][h][s/2] pairs along s
__device__ uint32_t g_Vtlp[BB * 64 * 1024];         // V^T lo
__device__ __nv_bfloat16 g_Bh[192 * 1024];          // weights hi  [n][k]
__device__ __nv_bfloat16 g_Bl[192 * 1024];          // weights lo
__device__ float g_qkvp[2 * 16384 * 192];           // split-K GEMM partials (25.2 MB)

// Split-K attention partials.
__device__ float g_pO[BB * 32 * 4 * 64 * 64];       // 16.8 MB
__device__ float g_pm[BB * 32 * 4 * 64];
__device__ float g_pl[BB * 32 * 4 * 64];

// ---------------------------------------------------------------------------
__device__ __forceinline__ void tsplit2(float a, float b, uint32_t& hi, uint32_t& lo) {
    uint32_t ia = __float_as_uint(a), ib = __float_as_uint(b);
    hi = __byte_perm(ia, ib, 0x7632);
    float ra = a - __uint_as_float(ia & 0xFFFF0000u);
    float rb = b - __uint_as_float(ib & 0xFFFF0000u);
    asm("cvt.rn.bf16x2.f32 %0, %1, %2;" : "=r"(lo) : "f"(rb), "f"(ra));
}

__device__ __forceinline__ float exp2_fast(float x) {
    x = fmaxf(x, -80.0f);
    float z = x + 12582912.0f;
    float n = z - 12582912.0f;
    float f = x - n;
    float p =            1.3333558e-3f;
    p = fmaf(p, f, 9.6181291e-3f);
    p = fmaf(p, f, 5.5504109e-2f);
    p = fmaf(p, f, 2.4022650e-1f);
    p = fmaf(p, f, 6.9314718e-1f);
    p = fmaf(p, f, 1.0f);
    int e = __float_as_int(z);
    float sc = __int_as_float((e + (127 - 0x4B400000)) << 23);
    return p * sc;
}

__device__ __forceinline__ void mma_bf16(float c[4],
                                         uint32_t a0, uint32_t a1, uint32_t a2, uint32_t a3,
                                         uint32_t b0, uint32_t b1) {
    asm volatile(
        "mma.sync.aligned.m16n8k16.row.col.f32.bf16.bf16.f32 "
        "{%0,%1,%2,%3}, {%4,%5,%6,%7}, {%8,%9}, {%0,%1,%2,%3};"
        : "+f"(c[0]), "+f"(c[1]), "+f"(c[2]), "+f"(c[3])
        : "r"(a0), "r"(a1), "r"(a2), "r"(a3), "r"(b0), "r"(b1));
}

__device__ __forceinline__ uint32_t lds32(const __nv_bfloat16* p) {
    return *(const uint32_t*)p;
}

// ---------------------------------------------------------------------------
// Kernel 0: split weights.
// ---------------------------------------------------------------------------
__global__ void prep_w(const float* __restrict__ Wq,
                       const float* __restrict__ Wk,
                       const float* __restrict__ Wv)
{
    int i = blockIdx.x * blockDim.x + threadIdx.x;
    int n = i >> 10;
    int k = i & 1023;
    int m = n >> 6;
    int col = n & 63;
    const float* W = (m == 0) ? Wq : (m == 1) ? Wk : Wv;
    float w = W[k * 64 + col];
    __nv_bfloat16 h = __float2bfloat16(w);
    float lo = w - __bfloat162float(h);
    g_Bh[(size_t)n * 1024 + k] = h;
    g_Bl[(size_t)n * 1024 + k] = __float2bfloat16(lo);
}

// ---------------------------------------------------------------------------
// Kernel 1: QKV projection, SPLIT-K. Grid (128 m-tiles, 2 k-halves).
// Exact R10 inner config: 256 threads, warp 32x96, M=128, chunk 32.
// Each CTA covers K in [kv*512, kv*512+512) (16 chunks) and writes fp32
// partials to g_qkvp. 256 CTAs -> all SMs busy, ~2 CTAs/SM.
// ---------------------------------------------------------------------------
#define APITCH 36
#define BPITCH 36

__global__ __launch_bounds__(256) void qkv_mma(const float* __restrict__ x)
{
    __shared__ __align__(16) __nv_bfloat16 Ah[128 * APITCH];
    __shared__ __align__(16) __nv_bfloat16 Al[128 * APITCH];
    __shared__ __align__(16) __nv_bfloat16 Bh[192 * BPITCH];
    __shared__ __align__(16) __nv_bfloat16 Bl[192 * BPITCH];

    const int tid = threadIdx.x;
    const int wid = tid >> 5;
    const int lane = tid & 31;
    const int grow = lane >> 2;
    const int tg = lane & 3;
    const int warp_m = wid & 3;
    const int warp_n = wid >> 2;
    const int row0 = blockIdx.x * 128;
    const int kv = blockIdx.y;           // k-half

    float acc[2][12][4] = {};

    const int kend = kv * 512 + 512;
    for (int k0 = kv * 512; k0 < kend; k0 += 32) {
        #pragma unroll
        for (int i = 0; i < 4; i++) {
            int idx = tid + (i << 8);
            int r = idx >> 3;
            int c4 = idx & 7;
            float4 f = *(const float4*)(x + (size_t)(row0 + r) * DD + k0 + c4 * 4);
            uint32_t h01, l01, h23, l23;
            tsplit2(f.x, f.y, h01, l01);
            tsplit2(f.z, f.w, h23, l23);
            int off = r * APITCH + c4 * 4;
            *(uint2*)&Ah[off] = make_uint2(h01, h23);
            *(uint2*)&Al[off] = make_uint2(l01, l23);
        }
        #pragma unroll
        for (int i = 0; i < 3; i++) {
            int idx = tid + (i << 8);
            int r = idx >> 2;
            int q = idx & 3;
            int off = r * BPITCH + q * 8;
            uint4 vh = *(const uint4*)(g_Bh + (size_t)r * 1024 + k0 + q * 8);
            uint4 vl = *(const uint4*)(g_Bl + (size_t)r * 1024 + k0 + q * 8);
            *(uint2*)&Bh[off]     = make_uint2(vh.x, vh.y);
            *(uint2*)&Bh[off + 4] = make_uint2(vh.z, vh.w);
            *(uint2*)&Bl[off]     = make_uint2(vl.x, vl.y);
            *(uint2*)&Bl[off + 4] = make_uint2(vl.z, vl.w);
        }
        __syncthreads();

        #pragma unroll
        for (int ks = 0; ks < 2; ks++) {
            const int kofs = ks * 16 + tg * 2;
            uint32_t ah[2][4], al[2][4];
            #pragma unroll
            for (int mt = 0; mt < 2; mt++) {
                int rb = (warp_m * 32 + mt * 16 + grow) * APITCH + kofs;
                ah[mt][0] = lds32(Ah + rb);
                ah[mt][1] = lds32(Ah + rb + 8 * APITCH);
                ah[mt][2] = lds32(Ah + rb + 8);
                ah[mt][3] = lds32(Ah + rb + 8 * APITCH + 8);
                al[mt][0] = lds32(Al + rb);
                al[mt][1] = lds32(Al + rb + 8 * APITCH);
                al[mt][2] = lds32(Al + rb + 8);
                al[mt][3] = lds32(Al + rb + 8 * APITCH + 8);
            }
            #pragma unroll
            for (int nt = 0; nt < 12; nt++) {
                int cb = (warp_n * 96 + nt * 8 + grow) * BPITCH + kofs;
                uint32_t bh0 = lds32(Bh + cb);
                uint32_t bh1 = lds32(Bh + cb + 8);
                uint32_t bl0 = lds32(Bl + cb);
                uint32_t bl1 = lds32(Bl + cb + 8);
                #pragma unroll
                for (int mt = 0; mt < 2; mt++) {
                    mma_bf16(acc[mt][nt], ah[mt][0], ah[mt][1], ah[mt][2], ah[mt][3], bh0, bh1);
                    mma_bf16(acc[mt][nt], ah[mt][0], ah[mt][1], ah[mt][2], ah[mt][3], bl0, bl1);
                    mma_bf16(acc[mt][nt], al[mt][0], al[mt][1], al[mt][2], al[mt][3], bh0, bh1);
                }
            }
        }
        __syncthreads();
    }

    // Write fp32 partials (no routing — combine kernel handles that).
    float* pp = g_qkvp + (size_t)kv * 16384 * 192;
    #pragma unroll
    for (int mt = 0; mt < 2; mt++) {
        int r = row0 + warp_m * 32 + mt * 16 + grow;
        #pragma unroll
        for (int nt = 0; nt < 12; nt++) {
            int col = warp_n * 96 + nt * 8 + tg * 2;
            *(float2*)(pp + (size_t)r * 192 + col) =
                make_float2(acc[mt][nt][0], acc[mt][nt][1]);
            *(float2*)(pp + (size_t)(r + 8) * 192 + col) =
                make_float2(acc[mt][nt][2], acc[mt][nt][3]);
        }
    }
}

// ---------------------------------------------------------------------------
// Kernel 1b: combine the two K-half partials and route:
//   cols 0..63   -> g_Q fp32
//   cols 64..127 -> K bf16 hi/lo pairs along h
//   cols 128..191-> V^T bf16 hi/lo pairs along s (transpose via smem)
// Grid 256 CTAs (one per 64-row tile), 256 threads. smem pitch 193 (odd):
// conflict-free-ish column reads for the V transpose.
// ---------------------------------------------------------------------------
__global__ __launch_bounds__(256) void qkv_combine()
{
    __shared__ float sm[64 * 193];
    const int tid = threadIdx.x;
    const int tile = blockIdx.x;         // 0..255
    const int row0 = tile * 64;
    const int b  = row0 >> 11;           // /2048
    const int s0 = row0 & 2047;

    // Load + sum both partials: 64 x 192 = 3072 float4, 12 per thread.
    #pragma unroll
    for (int i = 0; i < 12; i++) {
        int idx = tid + (i << 8);
        int r = idx / 48;
        int c4 = (idx % 48) * 4;
        const float* p0 = g_qkvp + (size_t)(row0 + r) * 192 + c4;
        float4 a = *(const float4*)p0;
        float4 bq = *(const float4*)(p0 + (size_t)16384 * 192);
        sm[r * 193 + c4 + 0] = a.x + bq.x;
        sm[r * 193 + c4 + 1] = a.y + bq.y;
        sm[r * 193 + c4 + 2] = a.z + bq.z;
        sm[r * 193 + c4 + 3] = a.w + bq.w;
    }
    __syncthreads();

    // Q: cols 0..63, row-major copy (1024 float4).
    #pragma unroll
    for (int i = 0; i < 4; i++) {
        int idx = tid + (i << 8);
        int r = idx >> 4;
        int c4 = (idx & 15) << 2;
        float* s = &sm[r * 193 + c4];
        *(float4*)(g_Q + (size_t)(row0 + r) * 64 + c4) =
            make_float4(s[0], s[1], s[2], s[3]);
    }

    // K: cols 64..127 -> pairs along h. 64 rows x 32 pairs = 2048.
    #pragma unroll
    for (int i = 0; i < 8; i++) {
        int idx = tid + (i << 8);
        int r = idx >> 5;
        int p = idx & 31;
        float a = sm[r * 193 + 64 + 2 * p];
        float c = sm[r * 193 + 64 + 2 * p + 1];
        uint32_t hi, lo;
        tsplit2(a, c, hi, lo);
        g_Khp[(size_t)(row0 + r) * 32 + p] = hi;
        g_Klp[(size_t)(row0 + r) * 32 + p] = lo;
    }

    // V^T: cols 128..191 -> [b][h][s/2] pairs along s. 64 h x 32 s-pairs.
    #pragma unroll
    for (int i = 0; i < 8; i++) {
        int idx = tid + (i << 8);
        int h  = idx >> 5;
        int sp = idx & 31;
        float v0 = sm[(2 * sp) * 193 + 128 + h];
        float v1 = sm[(2 * sp + 1) * 193 + 128 + h];
        uint32_t hi, lo;
        tsplit2(v0, v1, hi, lo);
        size_t o = (size_t)(b * 64 + h) * 1024 + (s0 >> 1) + sp;
        g_Vthp[o] = hi;
        g_Vtlp[o] = lo;
    }
}

// ---------------------------------------------------------------------------
// Kernel 2a: split-K flash attention partials (exact R10 version).
// ---------------------------------------------------------------------------
#define KPITCH 72
#define SCL 0.18033688011112042f   /* 0.125 * log2(e) */

__global__ __launch_bounds__(128) void attn_part(float* __restrict__ dummy)
{
    __shared__ __align__(16) __nv_bfloat16 Kh[64 * KPITCH];
    __shared__ __align__(16) __nv_bfloat16 Kl[64 * KPITCH];
    __shared__ __align__(16) __nv_bfloat16 Vth[64 * KPITCH];
    __shared__ __align__(16) __nv_bfloat16 Vtl[64 * KPITCH];
    (void)dummy;

    const int tid = threadIdx.x;
    const int wm = tid >> 5;
    const int lane = tid & 31;
    const int grow = lane >> 2;
    const int tg = lane & 3;
    const int u = blockIdx.x;
    const int b = blockIdx.y;

    int qb, ci;
    if (u < 8)       { qb = u;                 ci = 0; }
    else if (u < 24) { qb = 8  + ((u - 8) >> 1);  ci = (u - 8) & 1; }
    else if (u < 48) { qb = 16 + (u - 24) / 3;    ci = (u - 24) % 3; }
    else             { qb = 24 + ((u - 48) >> 2); ci = (u - 48) & 3; }

    const int kb0 = ci * 8;
    const int kb1 = min(kb0 + 7, qb);

    const float* Qg = g_Q + (size_t)(b * SS + qb * 64 + wm * 16) * HH;

    uint32_t qh[4][4], ql[4][4];
    #pragma unroll
    for (int kt = 0; kt < 4; kt++) {
        float2 v00 = *(const float2*)(Qg + grow * HH + kt * 16 + tg * 2);
        float2 v10 = *(const float2*)(Qg + (grow + 8) * HH + kt * 16 + tg * 2);
        float2 v01 = *(const float2*)(Qg + grow * HH + kt * 16 + tg * 2 + 8);
        float2 v11 = *(const float2*)(Qg + (grow + 8) * HH + kt * 16 + tg * 2 + 8);
        tsplit2(v00.x, v00.y, qh[kt][0], ql[kt][0]);
        tsplit2(v10.x, v10.y, qh[kt][1], ql[kt][1]);
        tsplit2(v01.x, v01.y, qh[kt][2], ql[kt][2]);
        tsplit2(v11.x, v11.y, qh[kt][3], ql[kt][3]);
    }

    float o[8][4] = {};
    float m0 = -1e30f, m1 = -1e30f, l0 = 0.0f, l1 = 0.0f;
    const int qr0 = qb * 64 + wm * 16 + grow;

    const uint4* Khg4 = (const uint4*)(g_Khp + (size_t)b * SS * 32);
    const uint4* Klg4 = (const uint4*)(g_Klp + (size_t)b * SS * 32);
    const uint4* Vhg4 = (const uint4*)(g_Vthp + (size_t)b * 64 * 1024);
    const uint4* Vlg4 = (const uint4*)(g_Vtlp + (size_t)b * 64 * 1024);

    for (int kb = kb0; kb <= kb1; kb++) {
        #pragma unroll
        for (int i = 0; i < 4; i++) {
            int idx = tid + (i << 7);
            int r = idx >> 3, q = idx & 7;
            *(uint4*)&Kh[r * KPITCH + q * 8]  = Khg4[(size_t)(kb * 64 + r) * 8 + q];
            *(uint4*)&Kl[r * KPITCH + q * 8]  = Klg4[(size_t)(kb * 64 + r) * 8 + q];
            *(uint4*)&Vth[r * KPITCH + q * 8] = Vhg4[(size_t)r * 256 + kb * 8 + q];
            *(uint4*)&Vtl[r * KPITCH + q * 8] = Vlg4[(size_t)r * 256 + kb * 8 + q];
        }
        __syncthreads();

        float s[8][4] = {};
        #pragma unroll
        for (int nt = 0; nt < 8; nt++) {
            #pragma unroll
            for (int kt = 0; kt < 4; kt++) {
                int cb = (nt * 8 + grow) * KPITCH + kt * 16 + tg * 2;
                uint32_t bh0 = lds32(Kh + cb), bh1 = lds32(Kh + cb + 8);
                uint32_t bl0 = lds32(Kl + cb), bl1 = lds32(Kl + cb + 8);
                mma_bf16(s[nt], qh[kt][0], qh[kt][1], qh[kt][2], qh[kt][3], bh0, bh1);
                mma_bf16(s[nt], qh[kt][0], qh[kt][1], qh[kt][2], qh[kt][3], bl0, bl1);
                mma_bf16(s[nt], ql[kt][0], ql[kt][1], ql[kt][2], ql[kt][3], bh0, bh1);
            }
        }

        if (kb == qb) {
            #pragma unroll
            for (int nt = 0; nt < 8; nt++) {
                int kc = kb * 64 + nt * 8 + tg * 2;
                s[nt][0] = (kc     > qr0)     ? -1e30f : s[nt][0] * SCL;
                s[nt][1] = (kc + 1 > qr0)     ? -1e30f : s[nt][1] * SCL;
                s[nt][2] = (kc     > qr0 + 8) ? -1e30f : s[nt][2] * SCL;
                s[nt][3] = (kc + 1 > qr0 + 8) ? -1e30f : s[nt][3] * SCL;
            }
        } else {
            #pragma unroll
            for (int nt = 0; nt < 8; nt++) {
                s[nt][0] *= SCL; s[nt][1] *= SCL;
                s[nt][2] *= SCL; s[nt][3] *= SCL;
            }
        }

        float mx0 = -1e30f, mx1 = -1e30f;
        #pragma unroll
        for (int nt = 0; nt < 8; nt++) {
            mx0 = fmaxf(mx0, fmaxf(s[nt][0], s[nt][1]));
            mx1 = fmaxf(mx1, fmaxf(s[nt][2], s[nt][3]));
        }
        mx0 = fmaxf(mx0, __shfl_xor_sync(0xffffffffu, mx0, 1));
        mx0 = fmaxf(mx0, __shfl_xor_sync(0xffffffffu, mx0, 2));
        mx1 = fmaxf(mx1, __shfl_xor_sync(0xffffffffu, mx1, 1));
        mx1 = fmaxf(mx1, __shfl_xor_sync(0xffffffffu, mx1, 2));
        float nm0 = fmaxf(m0, mx0), nm1 = fmaxf(m1, mx1);
        float a0 = exp2_fast(m0 - nm0), a1 = exp2_fast(m1 - nm1);
        m0 = nm0; m1 = nm1;

        float rs0 = 0.0f, rs1 = 0.0f;
        #pragma unroll
        for (int nt = 0; nt < 8; nt++) {
            float p0 = exp2_fast(s[nt][0] - nm0);
            float p1 = exp2_fast(s[nt][1] - nm0);
            float p2 = exp2_fast(s[nt][2] - nm1);
            float p3 = exp2_fast(s[nt][3] - nm1);
            s[nt][0] = p0; s[nt][1] = p1; s[nt][2] = p2; s[nt][3] = p3;
            rs0 += p0 + p1;
            rs1 += p2 + p3;
        }
        rs0 += __shfl_xor_sync(0xffffffffu, rs0, 1);
        rs0 += __shfl_xor_sync(0xffffffffu, rs0, 2);
        rs1 += __shfl_xor_sync(0xffffffffu, rs1, 1);
        rs1 += __shfl_xor_sync(0xffffffffu, rs1, 2);
        l0 = l0 * a0 + rs0;
        l1 = l1 * a1 + rs1;
        #pragma unroll
        for (int nt = 0; nt < 8; nt++) {
            o[nt][0] *= a0; o[nt][1] *= a0;
            o[nt][2] *= a1; o[nt][3] *= a1;
        }

        #pragma unroll
        for (int kt = 0; kt < 4; kt++) {
            uint32_t ph[4], pl[4];
            tsplit2(s[2 * kt][0],     s[2 * kt][1],     ph[0], pl[0]);
            tsplit2(s[2 * kt][2],     s[2 * kt][3],     ph[1], pl[1]);
            tsplit2(s[2 * kt + 1][0], s[2 * kt + 1][1], ph[2], pl[2]);
            tsplit2(s[2 * kt + 1][2], s[2 * kt + 1][3], ph[3], pl[3]);
            #pragma unroll
            for (int nt = 0; nt < 8; nt++) {
                int cb = (nt * 8 + grow) * KPITCH + kt * 16 + tg * 2;
                uint32_t bh0 = lds32(Vth + cb), bh1 = lds32(Vth + cb + 8);
                uint32_t bl0 = lds32(Vtl + cb), bl1 = lds32(Vtl + cb + 8);
                mma_bf16(o[nt], ph[0], ph[1], ph[2], ph[3], bh0, bh1);
                mma_bf16(o[nt], ph[0], ph[1], ph[2], ph[3], bl0, bl1);
                mma_bf16(o[nt], pl[0], pl[1], pl[2], pl[3], bh0, bh1);
            }
        }
        __syncthreads();
    }

    const size_t unit = ((size_t)b * 32 + qb) * 4 + ci;
    float* pO = g_pO + unit * 4096 + (size_t)(wm * 16) * 64;
    #pragma unroll
    for (int nt = 0; nt < 8; nt++) {
        *(float2*)(pO + grow * 64 + nt * 8 + tg * 2) = make_float2(o[nt][0], o[nt][1]);
        *(float2*)(pO + (grow + 8) * 64 + nt * 8 + tg * 2) = make_float2(o[nt][2], o[nt][3]);
    }
    if (tg == 0) {
        g_pm[unit * 64 + wm * 16 + grow]     = m0;
        g_pm[unit * 64 + wm * 16 + grow + 8] = m1;
        g_pl[unit * 64 + wm * 16 + grow]     = l0;
        g_pl[unit * 64 + wm * 16 + grow + 8] = l1;
    }
}

// ---------------------------------------------------------------------------
// Kernel 2b: combine attention partials (exact R10 version).
// ---------------------------------------------------------------------------
__global__ __launch_bounds__(256) void attn_combine(float* __restrict__ Out)
{
    const int qb = blockIdx.x;
    const int b  = blockIdx.y;
    const int tid = threadIdx.x;
    const int r = tid >> 2;
    const int c0 = (tid & 3) * 16;
    const int nc = (qb >> 3) + 1;

    const size_t ubase = ((size_t)b * 32 + qb) * 4;

    float mi[4], li[4];
    float M = -1e30f;
    #pragma unroll 4
    for (int i = 0; i < nc; i++) {
        mi[i] = g_pm[(ubase + i) * 64 + r];
        li[i] = g_pl[(ubase + i) * 64 + r];
        M = fmaxf(M, mi[i]);
    }

    float acc[16] = {};
    float L = 0.0f;
    #pragma unroll 4
    for (int i = 0; i < nc; i++) {
        float al = exp2_fast(mi[i] - M);
        L += al * li[i];
        const float* pO = g_pO + (ubase + i) * 4096 + (size_t)r * 64 + c0;
        #pragma unroll
        for (int q = 0; q < 4; q++) {
            float4 v = *(const float4*)(pO + q * 4);
            acc[q * 4 + 0] += al * v.x;
            acc[q * 4 + 1] += al * v.y;
            acc[q * 4 + 2] += al * v.z;
            acc[q * 4 + 3] += al * v.w;
        }
    }

    float inv = 1.0f / L;
    float* Og = Out + (size_t)(b * SS + qb * 64 + r) * HH + c0;
    #pragma unroll
    for (int q = 0; q < 4; q++) {
        *(float4*)(Og + q * 4) = make_float4(acc[q * 4 + 0] * inv, acc[q * 4 + 1] * inv,
                                             acc[q * 4 + 2] * inv, acc[q * 4 + 3] * inv);
    }
}

// ---------------------------------------------------------------------------
extern "C" void kernel_launch(void* const* d_in, const int* in_sizes, int n_in,
                              void* d_out, int out_size)
{
    const float* x  = (const float*)d_in[0];
    const float* Wq = (const float*)d_in[1];
    const float* Wk = (const float*)d_in[2];
    const float* Wv = (const float*)d_in[3];
    float* out = (float*)d_out;
    (void)in_sizes; (void)n_in; (void)out_size;

    prep_w<<<768, 256>>>(Wq, Wk, Wv);
    qkv_mma<<<dim3(128, 2), 256>>>(x);
    qkv_combine<<<256, 256>>>();
    attn_part<<<dim3(80, BB), 128>>>(out);
    attn_combine<<<dim3(32, BB), 256>>>(out);
}

// round 13
// speedup vs baseline: 1.1129x; 1.0605x over previous
#include <cuda_runtime.h>
#include <cuda_bf16.h>
#include <math.h>
#include <stdint.h>

#define BB 8
#define SS 2048
#define DD 1024
#define HH 64

// Scratch.
__device__ float g_Q[BB * SS * HH];                 // fp32 Q
__device__ float g_V[BB * SS * HH];                 // fp32 V (input to prep_vt)
__device__ uint32_t g_Khp[BB * SS * 32];            // K hi, bf16x2 pairs along h
__device__ uint32_t g_Klp[BB * SS * 32];            // K lo
__device__ uint32_t g_Vthp[BB * 64 * 1024];         // V^T hi: [b][h][s/2] pairs along s
__device__ uint32_t g_Vtlp[BB * 64 * 1024];         // V^T lo
__device__ __nv_bfloat16 g_Bh[192 * 1024];          // weights hi  [n][k]
__device__ __nv_bfloat16 g_Bl[192 * 1024];          // weights lo

// Split-K attention partials.
__device__ float g_pO[BB * 32 * 4 * 64 * 64];       // 16.8 MB
__device__ float g_pm[BB * 32 * 4 * 64];
__device__ float g_pl[BB * 32 * 4 * 64];

// ---------------------------------------------------------------------------
__device__ __forceinline__ void tsplit2(float a, float b, uint32_t& hi, uint32_t& lo) {
    uint32_t ia = __float_as_uint(a), ib = __float_as_uint(b);
    hi = __byte_perm(ia, ib, 0x7632);
    float ra = a - __uint_as_float(ia & 0xFFFF0000u);
    float rb = b - __uint_as_float(ib & 0xFFFF0000u);
    asm("cvt.rn.bf16x2.f32 %0, %1, %2;" : "=r"(lo) : "f"(rb), "f"(ra));
}

__device__ __forceinline__ float exp2_fast(float x) {
    x = fmaxf(x, -80.0f);
    float z = x + 12582912.0f;
    float n = z - 12582912.0f;
    float f = x - n;
    float p =            1.3333558e-3f;
    p = fmaf(p, f, 9.6181291e-3f);
    p = fmaf(p, f, 5.5504109e-2f);
    p = fmaf(p, f, 2.4022650e-1f);
    p = fmaf(p, f, 6.9314718e-1f);
    p = fmaf(p, f, 1.0f);
    int e = __float_as_int(z);
    float sc = __int_as_float((e + (127 - 0x4B400000)) << 23);
    return p * sc;
}

__device__ __forceinline__ void mma_bf16(float c[4],
                                         uint32_t a0, uint32_t a1, uint32_t a2, uint32_t a3,
                                         uint32_t b0, uint32_t b1) {
    asm volatile(
        "mma.sync.aligned.m16n8k16.row.col.f32.bf16.bf16.f32 "
        "{%0,%1,%2,%3}, {%4,%5,%6,%7}, {%8,%9}, {%0,%1,%2,%3};"
        : "+f"(c[0]), "+f"(c[1]), "+f"(c[2]), "+f"(c[3])
        : "r"(a0), "r"(a1), "r"(a2), "r"(a3), "r"(b0), "r"(b1));
}

__device__ __forceinline__ uint32_t lds32(const __nv_bfloat16* p) {
    return *(const uint32_t*)p;
}

// ---------------------------------------------------------------------------
// Kernel 0: split weights.
// ---------------------------------------------------------------------------
__global__ void prep_w(const float* __restrict__ Wq,
                       const float* __restrict__ Wk,
                       const float* __restrict__ Wv)
{
    int i = blockIdx.x * blockDim.x + threadIdx.x;
    int n = i >> 10;
    int k = i & 1023;
    int m = n >> 6;
    int col = n & 63;
    const float* W = (m == 0) ? Wq : (m == 1) ? Wk : Wv;
    float w = W[k * 64 + col];
    __nv_bfloat16 h = __float2bfloat16(w);
    float lo = w - __bfloat162float(h);
    g_Bh[(size_t)n * 1024 + k] = h;
    g_Bl[(size_t)n * 1024 + k] = __float2bfloat16(lo);
}

// ---------------------------------------------------------------------------
// Kernel 1: QKV projection, double-buffered smem + A-register-prefetch.
// M=128, N=192, chunk 32, 256 threads, warp 32x96 (R10 inner loop).
// Dynamic smem: 2 stages x {Ah,Al[128x36], Bh,Bl[192x36]} bf16 = 92160 B.
// One __syncthreads per chunk; A LDGs for chunk c+1 issue before MMAs of c.
// ---------------------------------------------------------------------------
#define APITCH 36
#define BPITCH 36
#define QSTAGE 46080
#define QA_OFF 0
#define QAL_OFF 9216
#define QB_OFF 18432
#define QBL_OFF 32256
#define QKV_SMEM (2 * QSTAGE)

__global__ __launch_bounds__(256) void qkv_mma(const float* __restrict__ x)
{
    extern __shared__ __align__(16) char qsm[];

    const int tid = threadIdx.x;
    const int wid = tid >> 5;
    const int lane = tid & 31;
    const int grow = lane >> 2;
    const int tg = lane & 3;
    const int warp_m = wid & 3;
    const int warp_n = wid >> 2;
    const int row0 = blockIdx.x * 128;

    // Per-thread A-load coordinates (4 float4 per chunk).
    int ar[4], ac[4];
    #pragma unroll
    for (int i = 0; i < 4; i++) {
        int idx = tid + (i << 8);
        ar[i] = idx >> 3;
        ac[i] = (idx & 7) * 4;
    }
    // Per-thread B-load coordinates (3 uint4-pairs per chunk).
    int br[3], bq[3];
    #pragma unroll
    for (int i = 0; i < 3; i++) {
        int idx = tid + (i << 8);
        br[i] = idx >> 2;
        bq[i] = idx & 3;
    }

    float acc[2][12][4] = {};
    float4 fA[4];

    // Prologue: load + store chunk 0.
    #pragma unroll
    for (int i = 0; i < 4; i++)
        fA[i] = *(const float4*)(x + (size_t)(row0 + ar[i]) * DD + ac[i]);
    {
        char* st = qsm;
        #pragma unroll
        for (int i = 0; i < 4; i++) {
            uint32_t h01, l01, h23, l23;
            tsplit2(fA[i].x, fA[i].y, h01, l01);
            tsplit2(fA[i].z, fA[i].w, h23, l23);
            int off = (ar[i] * APITCH + ac[i]) * 2;
            *(uint2*)(st + QA_OFF + off)  = make_uint2(h01, h23);
            *(uint2*)(st + QAL_OFF + off) = make_uint2(l01, l23);
        }
        #pragma unroll
        for (int i = 0; i < 3; i++) {
            uint4 vh = *(const uint4*)(g_Bh + (size_t)br[i] * 1024 + bq[i] * 8);
            uint4 vl = *(const uint4*)(g_Bl + (size_t)br[i] * 1024 + bq[i] * 8);
            int off = (br[i] * BPITCH + bq[i] * 8) * 2;
            *(uint2*)(st + QB_OFF + off)      = make_uint2(vh.x, vh.y);
            *(uint2*)(st + QB_OFF + off + 8)  = make_uint2(vh.z, vh.w);
            *(uint2*)(st + QBL_OFF + off)     = make_uint2(vl.x, vl.y);
            *(uint2*)(st + QBL_OFF + off + 8) = make_uint2(vl.z, vl.w);
        }
    }
    __syncthreads();

    for (int c = 0; c < 32; c++) {
        const int k1 = (c + 1) * 32;
        // Prefetch next A chunk into registers (LDGs fly during MMAs).
        if (k1 < DD) {
            #pragma unroll
            for (int i = 0; i < 4; i++)
                fA[i] = *(const float4*)(x + (size_t)(row0 + ar[i]) * DD + k1 + ac[i]);
        }

        const char* cur = qsm + (c & 1) * QSTAGE;
        const __nv_bfloat16* Ah = (const __nv_bfloat16*)(cur + QA_OFF);
        const __nv_bfloat16* Al = (const __nv_bfloat16*)(cur + QAL_OFF);
        const __nv_bfloat16* Bh = (const __nv_bfloat16*)(cur + QB_OFF);
        const __nv_bfloat16* Bl = (const __nv_bfloat16*)(cur + QBL_OFF);

        #pragma unroll
        for (int ks = 0; ks < 2; ks++) {
            const int kofs = ks * 16 + tg * 2;
            uint32_t ah[2][4], al[2][4];
            #pragma unroll
            for (int mt = 0; mt < 2; mt++) {
                int rb = (warp_m * 32 + mt * 16 + grow) * APITCH + kofs;
                ah[mt][0] = lds32(Ah + rb);
                ah[mt][1] = lds32(Ah + rb + 8 * APITCH);
                ah[mt][2] = lds32(Ah + rb + 8);
                ah[mt][3] = lds32(Ah + rb + 8 * APITCH + 8);
                al[mt][0] = lds32(Al + rb);
                al[mt][1] = lds32(Al + rb + 8 * APITCH);
                al[mt][2] = lds32(Al + rb + 8);
                al[mt][3] = lds32(Al + rb + 8 * APITCH + 8);
            }
            #pragma unroll
            for (int nt = 0; nt < 12; nt++) {
                int cb = (warp_n * 96 + nt * 8 + grow) * BPITCH + kofs;
                uint32_t bh0 = lds32(Bh + cb);
                uint32_t bh1 = lds32(Bh + cb + 8);
                uint32_t bl0 = lds32(Bl + cb);
                uint32_t bl1 = lds32(Bl + cb + 8);
                #pragma unroll
                for (int mt = 0; mt < 2; mt++) {
                    mma_bf16(acc[mt][nt], ah[mt][0], ah[mt][1], ah[mt][2], ah[mt][3], bh0, bh1);
                    mma_bf16(acc[mt][nt], ah[mt][0], ah[mt][1], ah[mt][2], ah[mt][3], bl0, bl1);
                    mma_bf16(acc[mt][nt], al[mt][0], al[mt][1], al[mt][2], al[mt][3], bh0, bh1);
                }
            }
        }

        // Store next chunk into the other stage (B loads here: L2-hot).
        if (k1 < DD) {
            char* st = qsm + ((c + 1) & 1) * QSTAGE;
            #pragma unroll
            for (int i = 0; i < 4; i++) {
                uint32_t h01, l01, h23, l23;
                tsplit2(fA[i].x, fA[i].y, h01, l01);
                tsplit2(fA[i].z, fA[i].w, h23, l23);
                int off = (ar[i] * APITCH + ac[i]) * 2;
                *(uint2*)(st + QA_OFF + off)  = make_uint2(h01, h23);
                *(uint2*)(st + QAL_OFF + off) = make_uint2(l01, l23);
            }
            #pragma unroll
            for (int i = 0; i < 3; i++) {
                uint4 vh = *(const uint4*)(g_Bh + (size_t)br[i] * 1024 + k1 + bq[i] * 8);
                uint4 vl = *(const uint4*)(g_Bl + (size_t)br[i] * 1024 + k1 + bq[i] * 8);
                int off = (br[i] * BPITCH + bq[i] * 8) * 2;
                *(uint2*)(st + QB_OFF + off)      = make_uint2(vh.x, vh.y);
                *(uint2*)(st + QB_OFF + off + 8)  = make_uint2(vh.z, vh.w);
                *(uint2*)(st + QBL_OFF + off)     = make_uint2(vl.x, vl.y);
                *(uint2*)(st + QBL_OFF + off + 8) = make_uint2(vl.z, vl.w);
            }
        }
        __syncthreads();
    }

    // Epilogue: Q,V fp32; K split once into bf16 hi/lo pair arrays.
    #pragma unroll
    for (int mt = 0; mt < 2; mt++) {
        int r = row0 + warp_m * 32 + mt * 16 + grow;
        #pragma unroll
        for (int nt = 0; nt < 12; nt++) {
            int col = warp_n * 96 + nt * 8 + tg * 2;
            int mat = col >> 6;
            int c = col & 63;
            if (mat == 1) {
                uint32_t h0, l0, h1, l1;
                tsplit2(acc[mt][nt][0], acc[mt][nt][1], h0, l0);
                tsplit2(acc[mt][nt][2], acc[mt][nt][3], h1, l1);
                int pidx = c >> 1;
                g_Khp[(size_t)r * 32 + pidx] = h0;
                g_Klp[(size_t)r * 32 + pidx] = l0;
                g_Khp[(size_t)(r + 8) * 32 + pidx] = h1;
                g_Klp[(size_t)(r + 8) * 32 + pidx] = l1;
            } else {
                float* dst = (mat == 0) ? g_Q : g_V;
                *(float2*)(dst + (size_t)r * 64 + c) =
                    make_float2(acc[mt][nt][0], acc[mt][nt][1]);
                *(float2*)(dst + (size_t)(r + 8) * 64 + c) =
                    make_float2(acc[mt][nt][2], acc[mt][nt][3]);
            }
        }
    }
}

// ---------------------------------------------------------------------------
// Kernel 1b: transpose + split V once.
// ---------------------------------------------------------------------------
__global__ __launch_bounds__(256) void prep_vt()
{
    __shared__ float vt[64 * 65];
    const int tid = threadIdx.x;
    const int s0 = blockIdx.x * 64;
    const int b  = blockIdx.y;

    #pragma unroll
    for (int i = 0; i < 4; i++) {
        int idx = tid + (i << 8);
        int r = idx >> 4;
        int c4 = (idx & 15) << 2;
        float4 f = *(const float4*)(g_V + (size_t)(b * SS + s0 + r) * 64 + c4);
        vt[r * 65 + c4 + 0] = f.x;  vt[r * 65 + c4 + 1] = f.y;
        vt[r * 65 + c4 + 2] = f.z;  vt[r * 65 + c4 + 3] = f.w;
    }
    __syncthreads();

    #pragma unroll
    for (int i = 0; i < 8; i++) {
        int idx = tid + (i << 8);
        int h  = idx >> 5;
        int sp = idx & 31;
        float v0 = vt[(sp * 2 + 0) * 65 + h];
        float v1 = vt[(sp * 2 + 1) * 65 + h];
        uint32_t hi, lo;
        tsplit2(v0, v1, hi, lo);
        size_t o = (size_t)(b * 64 + h) * 1024 + (s0 >> 1) + sp;
        g_Vthp[o] = hi;
        g_Vtlp[o] = lo;
    }
}

// ---------------------------------------------------------------------------
// Kernel 2a: split-K flash attention partials (exact R10 version).
// ---------------------------------------------------------------------------
#define KPITCH 72
#define SCL 0.18033688011112042f   /* 0.125 * log2(e) */

__global__ __launch_bounds__(128) void attn_part(float* __restrict__ dummy)
{
    __shared__ __align__(16) __nv_bfloat16 Kh[64 * KPITCH];
    __shared__ __align__(16) __nv_bfloat16 Kl[64 * KPITCH];
    __shared__ __align__(16) __nv_bfloat16 Vth[64 * KPITCH];
    __shared__ __align__(16) __nv_bfloat16 Vtl[64 * KPITCH];
    (void)dummy;

    const int tid = threadIdx.x;
    const int wm = tid >> 5;
    const int lane = tid & 31;
    const int grow = lane >> 2;
    const int tg = lane & 3;
    const int u = blockIdx.x;
    const int b = blockIdx.y;

    int qb, ci;
    if (u < 8)       { qb = u;                 ci = 0; }
    else if (u < 24) { qb = 8  + ((u - 8) >> 1);  ci = (u - 8) & 1; }
    else if (u < 48) { qb = 16 + (u - 24) / 3;    ci = (u - 24) % 3; }
    else             { qb = 24 + ((u - 48) >> 2); ci = (u - 48) & 3; }

    const int kb0 = ci * 8;
    const int kb1 = min(kb0 + 7, qb);

    const float* Qg = g_Q + (size_t)(b * SS + qb * 64 + wm * 16) * HH;

    uint32_t qh[4][4], ql[4][4];
    #pragma unroll
    for (int kt = 0; kt < 4; kt++) {
        float2 v00 = *(const float2*)(Qg + grow * HH + kt * 16 + tg * 2);
        float2 v10 = *(const float2*)(Qg + (grow + 8) * HH + kt * 16 + tg * 2);
        float2 v01 = *(const float2*)(Qg + grow * HH + kt * 16 + tg * 2 + 8);
        float2 v11 = *(const float2*)(Qg + (grow + 8) * HH + kt * 16 + tg * 2 + 8);
        tsplit2(v00.x, v00.y, qh[kt][0], ql[kt][0]);
        tsplit2(v10.x, v10.y, qh[kt][1], ql[kt][1]);
        tsplit2(v01.x, v01.y, qh[kt][2], ql[kt][2]);
        tsplit2(v11.x, v11.y, qh[kt][3], ql[kt][3]);
    }

    float o[8][4] = {};
    float m0 = -1e30f, m1 = -1e30f, l0 = 0.0f, l1 = 0.0f;
    const int qr0 = qb * 64 + wm * 16 + grow;

    const uint4* Khg4 = (const uint4*)(g_Khp + (size_t)b * SS * 32);
    const uint4* Klg4 = (const uint4*)(g_Klp + (size_t)b * SS * 32);
    const uint4* Vhg4 = (const uint4*)(g_Vthp + (size_t)b * 64 * 1024);
    const uint4* Vlg4 = (const uint4*)(g_Vtlp + (size_t)b * 64 * 1024);

    for (int kb = kb0; kb <= kb1; kb++) {
        #pragma unroll
        for (int i = 0; i < 4; i++) {
            int idx = tid + (i << 7);
            int r = idx >> 3, q = idx & 7;
            *(uint4*)&Kh[r * KPITCH + q * 8]  = Khg4[(size_t)(kb * 64 + r) * 8 + q];
            *(uint4*)&Kl[r * KPITCH + q * 8]  = Klg4[(size_t)(kb * 64 + r) * 8 + q];
            *(uint4*)&Vth[r * KPITCH + q * 8] = Vhg4[(size_t)r * 256 + kb * 8 + q];
            *(uint4*)&Vtl[r * KPITCH + q * 8] = Vlg4[(size_t)r * 256 + kb * 8 + q];
        }
        __syncthreads();

        float s[8][4] = {};
        #pragma unroll
        for (int nt = 0; nt < 8; nt++) {
            #pragma unroll
            for (int kt = 0; kt < 4; kt++) {
                int cb = (nt * 8 + grow) * KPITCH + kt * 16 + tg * 2;
                uint32_t bh0 = lds32(Kh + cb), bh1 = lds32(Kh + cb + 8);
                uint32_t bl0 = lds32(Kl + cb), bl1 = lds32(Kl + cb + 8);
                mma_bf16(s[nt], qh[kt][0], qh[kt][1], qh[kt][2], qh[kt][3], bh0, bh1);
                mma_bf16(s[nt], qh[kt][0], qh[kt][1], qh[kt][2], qh[kt][3], bl0, bl1);
                mma_bf16(s[nt], ql[kt][0], ql[kt][1], ql[kt][2], ql[kt][3], bh0, bh1);
            }
        }

        if (kb == qb) {
            #pragma unroll
            for (int nt = 0; nt < 8; nt++) {
                int kc = kb * 64 + nt * 8 + tg * 2;
                s[nt][0] = (kc     > qr0)     ? -1e30f : s[nt][0] * SCL;
                s[nt][1] = (kc + 1 > qr0)     ? -1e30f : s[nt][1] * SCL;
                s[nt][2] = (kc     > qr0 + 8) ? -1e30f : s[nt][2] * SCL;
                s[nt][3] = (kc + 1 > qr0 + 8) ? -1e30f : s[nt][3] * SCL;
            }
        } else {
            #pragma unroll
            for (int nt = 0; nt < 8; nt++) {
                s[nt][0] *= SCL; s[nt][1] *= SCL;
                s[nt][2] *= SCL; s[nt][3] *= SCL;
            }
        }

        float mx0 = -1e30f, mx1 = -1e30f;
        #pragma unroll
        for (int nt = 0; nt < 8; nt++) {
            mx0 = fmaxf(mx0, fmaxf(s[nt][0], s[nt][1]));
            mx1 = fmaxf(mx1, fmaxf(s[nt][2], s[nt][3]));
        }
        mx0 = fmaxf(mx0, __shfl_xor_sync(0xffffffffu, mx0, 1));
        mx0 = fmaxf(mx0, __shfl_xor_sync(0xffffffffu, mx0, 2));
        mx1 = fmaxf(mx1, __shfl_xor_sync(0xffffffffu, mx1, 1));
        mx1 = fmaxf(mx1, __shfl_xor_sync(0xffffffffu, mx1, 2));
        float nm0 = fmaxf(m0, mx0), nm1 = fmaxf(m1, mx1);
        float a0 = exp2_fast(m0 - nm0), a1 = exp2_fast(m1 - nm1);
        m0 = nm0; m1 = nm1;

        float rs0 = 0.0f, rs1 = 0.0f;
        #pragma unroll
        for (int nt = 0; nt < 8; nt++) {
            float p0 = exp2_fast(s[nt][0] - nm0);
            float p1 = exp2_fast(s[nt][1] - nm0);
            float p2 = exp2_fast(s[nt][2] - nm1);
            float p3 = exp2_fast(s[nt][3] - nm1);
            s[nt][0] = p0; s[nt][1] = p1; s[nt][2] = p2; s[nt][3] = p3;
            rs0 += p0 + p1;
            rs1 += p2 + p3;
        }
        rs0 += __shfl_xor_sync(0xffffffffu, rs0, 1);
        rs0 += __shfl_xor_sync(0xffffffffu, rs0, 2);
        rs1 += __shfl_xor_sync(0xffffffffu, rs1, 1);
        rs1 += __shfl_xor_sync(0xffffffffu, rs1, 2);
        l0 = l0 * a0 + rs0;
        l1 = l1 * a1 + rs1;
        #pragma unroll
        for (int nt = 0; nt < 8; nt++) {
            o[nt][0] *= a0; o[nt][1] *= a0;
            o[nt][2] *= a1; o[nt][3] *= a1;
        }

        #pragma unroll
        for (int kt = 0; kt < 4; kt++) {
            uint32_t ph[4], pl[4];
            tsplit2(s[2 * kt][0],     s[2 * kt][1],     ph[0], pl[0]);
            tsplit2(s[2 * kt][2],     s[2 * kt][3],     ph[1], pl[1]);
            tsplit2(s[2 * kt + 1][0], s[2 * kt + 1][1], ph[2], pl[2]);
            tsplit2(s[2 * kt + 1][2], s[2 * kt + 1][3], ph[3], pl[3]);
            #pragma unroll
            for (int nt = 0; nt < 8; nt++) {
                int cb = (nt * 8 + grow) * KPITCH + kt * 16 + tg * 2;
                uint32_t bh0 = lds32(Vth + cb), bh1 = lds32(Vth + cb + 8);
                uint32_t bl0 = lds32(Vtl + cb), bl1 = lds32(Vtl + cb + 8);
                mma_bf16(o[nt], ph[0], ph[1], ph[2], ph[3], bh0, bh1);
                mma_bf16(o[nt], ph[0], ph[1], ph[2], ph[3], bl0, bl1);
                mma_bf16(o[nt], pl[0], pl[1], pl[2], pl[3], bh0, bh1);
            }
        }
        __syncthreads();
    }

    const size_t unit = ((size_t)b * 32 + qb) * 4 + ci;
    float* pO = g_pO + unit * 4096 + (size_t)(wm * 16) * 64;
    #pragma unroll
    for (int nt = 0; nt < 8; nt++) {
        *(float2*)(pO + grow * 64 + nt * 8 + tg * 2) = make_float2(o[nt][0], o[nt][1]);
        *(float2*)(pO + (grow + 8) * 64 + nt * 8 + tg * 2) = make_float2(o[nt][2], o[nt][3]);
    }
    if (tg == 0) {
        g_pm[unit * 64 + wm * 16 + grow]     = m0;
        g_pm[unit * 64 + wm * 16 + grow + 8] = m1;
        g_pl[unit * 64 + wm * 16 + grow]     = l0;
        g_pl[unit * 64 + wm * 16 + grow + 8] = l1;
    }
}

// ---------------------------------------------------------------------------
// Kernel 2b: combine attention partials (exact R10 version).
// ---------------------------------------------------------------------------
__global__ __launch_bounds__(256) void attn_combine(float* __restrict__ Out)
{
    const int qb = blockIdx.x;
    const int b  = blockIdx.y;
    const int tid = threadIdx.x;
    const int r = tid >> 2;
    const int c0 = (tid & 3) * 16;
    const int nc = (qb >> 3) + 1;

    const size_t ubase = ((size_t)b * 32 + qb) * 4;

    float mi[4], li[4];
    float M = -1e30f;
    #pragma unroll 4
    for (int i = 0; i < nc; i++) {
        mi[i] = g_pm[(ubase + i) * 64 + r];
        li[i] = g_pl[(ubase + i) * 64 + r];
        M = fmaxf(M, mi[i]);
    }

    float acc[16] = {};
    float L = 0.0f;
    #pragma unroll 4
    for (int i = 0; i < nc; i++) {
        float al = exp2_fast(mi[i] - M);
        L += al * li[i];
        const float* pO = g_pO + (ubase + i) * 4096 + (size_t)r * 64 + c0;
        #pragma unroll
        for (int q = 0; q < 4; q++) {
            float4 v = *(const float4*)(pO + q * 4);
            acc[q * 4 + 0] += al * v.x;
            acc[q * 4 + 1] += al * v.y;
            acc[q * 4 + 2] += al * v.z;
            acc[q * 4 + 3] += al * v.w;
        }
    }

    float inv = 1.0f / L;
    float* Og = Out + (size_t)(b * SS + qb * 64 + r) * HH + c0;
    #pragma unroll
    for (int q = 0; q < 4; q++) {
        *(float4*)(Og + q * 4) = make_float4(acc[q * 4 + 0] * inv, acc[q * 4 + 1] * inv,
                                             acc[q * 4 + 2] * inv, acc[q * 4 + 3] * inv);
    }
}

// ---------------------------------------------------------------------------
extern "C" void kernel_launch(void* const* d_in, const int* in_sizes, int n_in,
                              void* d_out, int out_size)
{
    const float* x  = (const float*)d_in[0];
    const float* Wq = (const float*)d_in[1];
    const float* Wk = (const float*)d_in[2];
    const float* Wv = (const float*)d_in[3];
    float* out = (float*)d_out;
    (void)in_sizes; (void)n_in; (void)out_size;

    cudaFuncSetAttribute(qkv_mma, cudaFuncAttributeMaxDynamicSharedMemorySize,
                         QKV_SMEM);

    prep_w<<<768, 256>>>(Wq, Wk, Wv);
    qkv_mma<<<(BB * SS) / 128, 256, QKV_SMEM>>>(x);
    prep_vt<<<dim3(SS / 64, BB), 256>>>();
    attn_part<<<dim3(80, BB), 128>>>(out);
    attn_combine<<<dim3(32, BB), 256>>>(out);
}

// round 14
// speedup vs baseline: 1.1483x; 1.0319x over previous
#include <cuda_runtime.h>
#include <cuda_bf16.h>
#include <math.h>
#include <stdint.h>

#define BB 8
#define SS 2048
#define DD 1024
#define HH 64

// Scratch.
__device__ float g_Q[BB * SS * HH];                 // fp32 Q
__device__ float g_V[BB * SS * HH];                 // fp32 V (input to prep_vt)
__device__ uint32_t g_Khp[BB * SS * 32];            // K hi, bf16x2 pairs along h
__device__ uint32_t g_Klp[BB * SS * 32];            // K lo
__device__ uint32_t g_Vthp[BB * 64 * 1024];         // V^T hi: [b][h][s/2] pairs along s
__device__ uint32_t g_Vtlp[BB * 64 * 1024];         // V^T lo
__device__ __nv_bfloat16 g_Bh[192 * 1024];          // weights hi  [n][k]
__device__ __nv_bfloat16 g_Bl[192 * 1024];          // weights lo

// Split-K attention partials.
__device__ float g_pO[BB * 32 * 4 * 64 * 64];       // 16.8 MB
__device__ float g_pm[BB * 32 * 4 * 64];
__device__ float g_pl[BB * 32 * 4 * 64];

// ---------------------------------------------------------------------------
__device__ __forceinline__ void tsplit2(float a, float b, uint32_t& hi, uint32_t& lo) {
    uint32_t ia = __float_as_uint(a), ib = __float_as_uint(b);
    hi = __byte_perm(ia, ib, 0x7632);
    float ra = a - __uint_as_float(ia & 0xFFFF0000u);
    float rb = b - __uint_as_float(ib & 0xFFFF0000u);
    asm("cvt.rn.bf16x2.f32 %0, %1, %2;" : "=r"(lo) : "f"(rb), "f"(ra));
}

__device__ __forceinline__ float exp2_fast(float x) {
    x = fmaxf(x, -80.0f);
    float z = x + 12582912.0f;
    float n = z - 12582912.0f;
    float f = x - n;
    float p =            1.3333558e-3f;
    p = fmaf(p, f, 9.6181291e-3f);
    p = fmaf(p, f, 5.5504109e-2f);
    p = fmaf(p, f, 2.4022650e-1f);
    p = fmaf(p, f, 6.9314718e-1f);
    p = fmaf(p, f, 1.0f);
    int e = __float_as_int(z);
    float sc = __int_as_float((e + (127 - 0x4B400000)) << 23);
    return p * sc;
}

__device__ __forceinline__ void mma_bf16(float c[4],
                                         uint32_t a0, uint32_t a1, uint32_t a2, uint32_t a3,
                                         uint32_t b0, uint32_t b1) {
    asm volatile(
        "mma.sync.aligned.m16n8k16.row.col.f32.bf16.bf16.f32 "
        "{%0,%1,%2,%3}, {%4,%5,%6,%7}, {%8,%9}, {%0,%1,%2,%3};"
        : "+f"(c[0]), "+f"(c[1]), "+f"(c[2]), "+f"(c[3])
        : "r"(a0), "r"(a1), "r"(a2), "r"(a3), "r"(b0), "r"(b1));
}

__device__ __forceinline__ void ldsm4(uint32_t& r0, uint32_t& r1,
                                      uint32_t& r2, uint32_t& r3, uint32_t saddr) {
    asm volatile("ldmatrix.sync.aligned.m8n8.x4.shared.b16 {%0,%1,%2,%3}, [%4];"
        : "=r"(r0), "=r"(r1), "=r"(r2), "=r"(r3) : "r"(saddr));
}

__device__ __forceinline__ uint32_t sptr(const void* p) {
    return (uint32_t)__cvta_generic_to_shared(p);
}

// ---------------------------------------------------------------------------
// Kernel 0: split weights.
// ---------------------------------------------------------------------------
__global__ void prep_w(const float* __restrict__ Wq,
                       const float* __restrict__ Wk,
                       const float* __restrict__ Wv)
{
    int i = blockIdx.x * blockDim.x + threadIdx.x;
    int n = i >> 10;
    int k = i & 1023;
    int m = n >> 6;
    int col = n & 63;
    const float* W = (m == 0) ? Wq : (m == 1) ? Wk : Wv;
    float w = W[k * 64 + col];
    __nv_bfloat16 h = __float2bfloat16(w);
    float lo = w - __bfloat162float(h);
    g_Bh[(size_t)n * 1024 + k] = h;
    g_Bl[(size_t)n * 1024 + k] = __float2bfloat16(lo);
}

// ---------------------------------------------------------------------------
// Kernel 1: QKV projection, double-buffered + A-prefetch + LDSM fragments.
// Pitch 40 bf16 (80 B): 16B-aligned rows for ldmatrix, conflict-free phases.
// ---------------------------------------------------------------------------
#define APITCH 40
#define QA_OFF  0
#define QAL_OFF 10240
#define QB_OFF  20480
#define QBL_OFF 35840
#define QSTAGE  51200
#define QKV_SMEM (2 * QSTAGE)

__global__ __launch_bounds__(256) void qkv_mma(const float* __restrict__ x)
{
    extern __shared__ __align__(16) char qsm[];

    const int tid = threadIdx.x;
    const int wid = tid >> 5;
    const int lane = tid & 31;
    const int grow = lane >> 2;
    const int tg = lane & 3;
    const int warp_m = wid & 3;
    const int warp_n = wid >> 2;
    const int row0 = blockIdx.x * 128;

    // LDSM lane-row offsets (bytes).
    const uint32_t alrow = (lane & 15) * 80 + (lane >> 4) * 16;
    const uint32_t blrow = ((lane & 7) + (lane >> 4) * 8) * 80 + ((lane >> 3) & 1) * 16;

    // Per-thread A-load coordinates (4 float4 per chunk).
    int ar[4], ac[4];
    #pragma unroll
    for (int i = 0; i < 4; i++) {
        int idx = tid + (i << 8);
        ar[i] = idx >> 3;
        ac[i] = (idx & 7) * 4;
    }
    // Per-thread B-load coordinates (3 uint4 per chunk per array).
    int br[3], bq[3];
    #pragma unroll
    for (int i = 0; i < 3; i++) {
        int idx = tid + (i << 8);
        br[i] = idx >> 2;
        bq[i] = idx & 3;
    }

    float acc[2][12][4] = {};
    float4 fA[4];

    auto store_chunk = [&](char* st, int k0) {
        #pragma unroll
        for (int i = 0; i < 4; i++) {
            uint32_t h01, l01, h23, l23;
            tsplit2(fA[i].x, fA[i].y, h01, l01);
            tsplit2(fA[i].z, fA[i].w, h23, l23);
            int off = ar[i] * 80 + ac[i] * 2;
            *(uint2*)(st + QA_OFF + off)  = make_uint2(h01, h23);
            *(uint2*)(st + QAL_OFF + off) = make_uint2(l01, l23);
        }
        #pragma unroll
        for (int i = 0; i < 3; i++) {
            uint4 vh = *(const uint4*)(g_Bh + (size_t)br[i] * 1024 + k0 + bq[i] * 8);
            uint4 vl = *(const uint4*)(g_Bl + (size_t)br[i] * 1024 + k0 + bq[i] * 8);
            int off = br[i] * 80 + bq[i] * 16;
            *(uint4*)(st + QB_OFF + off)  = vh;
            *(uint4*)(st + QBL_OFF + off) = vl;
        }
    };

    // Prologue: chunk 0.
    #pragma unroll
    for (int i = 0; i < 4; i++)
        fA[i] = *(const float4*)(x + (size_t)(row0 + ar[i]) * DD + ac[i]);
    store_chunk(qsm, 0);
    __syncthreads();

    for (int c = 0; c < 32; c++) {
        const int k1 = (c + 1) * 32;
        if (k1 < DD) {
            #pragma unroll
            for (int i = 0; i < 4; i++)
                fA[i] = *(const float4*)(x + (size_t)(row0 + ar[i]) * DD + k1 + ac[i]);
        }

        char* cur = qsm + (c & 1) * QSTAGE;
        const uint32_t AhS = sptr(cur + QA_OFF);
        const uint32_t AlS = sptr(cur + QAL_OFF);
        const uint32_t BhS = sptr(cur + QB_OFF);
        const uint32_t BlS = sptr(cur + QBL_OFF);

        #pragma unroll
        for (int ks = 0; ks < 2; ks++) {
            uint32_t ah[2][4], al[2][4];
            #pragma unroll
            for (int mt = 0; mt < 2; mt++) {
                uint32_t ra = (warp_m * 32 + mt * 16) * 80 + alrow + ks * 32;
                ldsm4(ah[mt][0], ah[mt][1], ah[mt][2], ah[mt][3], AhS + ra);
                ldsm4(al[mt][0], al[mt][1], al[mt][2], al[mt][3], AlS + ra);
            }
            #pragma unroll
            for (int p = 0; p < 6; p++) {
                uint32_t rb = (warp_n * 96 + p * 16) * 80 + blrow + ks * 32;
                uint32_t bh[4], bl[4];
                ldsm4(bh[0], bh[1], bh[2], bh[3], BhS + rb);
                ldsm4(bl[0], bl[1], bl[2], bl[3], BlS + rb);
                #pragma unroll
                for (int j = 0; j < 2; j++) {
                    int nt = 2 * p + j;
                    #pragma unroll
                    for (int mt = 0; mt < 2; mt++) {
                        mma_bf16(acc[mt][nt], ah[mt][0], ah[mt][1], ah[mt][2], ah[mt][3],
                                 bh[2 * j], bh[2 * j + 1]);
                        mma_bf16(acc[mt][nt], ah[mt][0], ah[mt][1], ah[mt][2], ah[mt][3],
                                 bl[2 * j], bl[2 * j + 1]);
                        mma_bf16(acc[mt][nt], al[mt][0], al[mt][1], al[mt][2], al[mt][3],
                                 bh[2 * j], bh[2 * j + 1]);
                    }
                }
            }
        }

        if (k1 < DD) store_chunk(qsm + ((c + 1) & 1) * QSTAGE, k1);
        __syncthreads();
    }

    // Epilogue: Q,V fp32; K split once into bf16 hi/lo pair arrays.
    #pragma unroll
    for (int mt = 0; mt < 2; mt++) {
        int r = row0 + warp_m * 32 + mt * 16 + grow;
        #pragma unroll
        for (int nt = 0; nt < 12; nt++) {
            int col = warp_n * 96 + nt * 8 + tg * 2;
            int mat = col >> 6;
            int c = col & 63;
            if (mat == 1) {
                uint32_t h0, l0, h1, l1;
                tsplit2(acc[mt][nt][0], acc[mt][nt][1], h0, l0);
                tsplit2(acc[mt][nt][2], acc[mt][nt][3], h1, l1);
                int pidx = c >> 1;
                g_Khp[(size_t)r * 32 + pidx] = h0;
                g_Klp[(size_t)r * 32 + pidx] = l0;
                g_Khp[(size_t)(r + 8) * 32 + pidx] = h1;
                g_Klp[(size_t)(r + 8) * 32 + pidx] = l1;
            } else {
                float* dst = (mat == 0) ? g_Q : g_V;
                *(float2*)(dst + (size_t)r * 64 + c) =
                    make_float2(acc[mt][nt][0], acc[mt][nt][1]);
                *(float2*)(dst + (size_t)(r + 8) * 64 + c) =
                    make_float2(acc[mt][nt][2], acc[mt][nt][3]);
            }
        }
    }
}

// ---------------------------------------------------------------------------
// Kernel 1b: transpose + split V once.
// ---------------------------------------------------------------------------
__global__ __launch_bounds__(256) void prep_vt()
{
    __shared__ float vt[64 * 65];
    const int tid = threadIdx.x;
    const int s0 = blockIdx.x * 64;
    const int b  = blockIdx.y;

    #pragma unroll
    for (int i = 0; i < 4; i++) {
        int idx = tid + (i << 8);
        int r = idx >> 4;
        int c4 = (idx & 15) << 2;
        float4 f = *(const float4*)(g_V + (size_t)(b * SS + s0 + r) * 64 + c4);
        vt[r * 65 + c4 + 0] = f.x;  vt[r * 65 + c4 + 1] = f.y;
        vt[r * 65 + c4 + 2] = f.z;  vt[r * 65 + c4 + 3] = f.w;
    }
    __syncthreads();

    #pragma unroll
    for (int i = 0; i < 8; i++) {
        int idx = tid + (i << 8);
        int h  = idx >> 5;
        int sp = idx & 31;
        float v0 = vt[(sp * 2 + 0) * 65 + h];
        float v1 = vt[(sp * 2 + 1) * 65 + h];
        uint32_t hi, lo;
        tsplit2(v0, v1, hi, lo);
        size_t o = (size_t)(b * 64 + h) * 1024 + (s0 >> 1) + sp;
        g_Vthp[o] = hi;
        g_Vtlp[o] = lo;
    }
}

// ---------------------------------------------------------------------------
// Kernel 2a: split-K flash attention partials, LDSM fragment loads.
// KPITCH 72 bf16 = 144 B rows (16B-aligned, conflict-free LDSM phases).
// ---------------------------------------------------------------------------
#define KPITCH 72
#define SCL 0.18033688011112042f   /* 0.125 * log2(e) */

__global__ __launch_bounds__(128) void attn_part(float* __restrict__ dummy)
{
    __shared__ __align__(16) __nv_bfloat16 Kh[64 * KPITCH];
    __shared__ __align__(16) __nv_bfloat16 Kl[64 * KPITCH];
    __shared__ __align__(16) __nv_bfloat16 Vth[64 * KPITCH];
    __shared__ __align__(16) __nv_bfloat16 Vtl[64 * KPITCH];
    (void)dummy;

    const int tid = threadIdx.x;
    const int wm = tid >> 5;
    const int lane = tid & 31;
    const int grow = lane >> 2;
    const int tg = lane & 3;
    const int u = blockIdx.x;
    const int b = blockIdx.y;

    int qb, ci;
    if (u < 8)       { qb = u;                 ci = 0; }
    else if (u < 24) { qb = 8  + ((u - 8) >> 1);  ci = (u - 8) & 1; }
    else if (u < 48) { qb = 16 + (u - 24) / 3;    ci = (u - 24) % 3; }
    else             { qb = 24 + ((u - 48) >> 2); ci = (u - 48) & 3; }

    const int kb0 = ci * 8;
    const int kb1 = min(kb0 + 7, qb);

    const float* Qg = g_Q + (size_t)(b * SS + qb * 64 + wm * 16) * HH;

    uint32_t qh[4][4], ql[4][4];
    #pragma unroll
    for (int kt = 0; kt < 4; kt++) {
        float2 v00 = *(const float2*)(Qg + grow * HH + kt * 16 + tg * 2);
        float2 v10 = *(const float2*)(Qg + (grow + 8) * HH + kt * 16 + tg * 2);
        float2 v01 = *(const float2*)(Qg + grow * HH + kt * 16 + tg * 2 + 8);
        float2 v11 = *(const float2*)(Qg + (grow + 8) * HH + kt * 16 + tg * 2 + 8);
        tsplit2(v00.x, v00.y, qh[kt][0], ql[kt][0]);
        tsplit2(v10.x, v10.y, qh[kt][1], ql[kt][1]);
        tsplit2(v01.x, v01.y, qh[kt][2], ql[kt][2]);
        tsplit2(v11.x, v11.y, qh[kt][3], ql[kt][3]);
    }

    float o[8][4] = {};
    float m0 = -1e30f, m1 = -1e30f, l0 = 0.0f, l1 = 0.0f;
    const int qr0 = qb * 64 + wm * 16 + grow;

    const uint4* Khg4 = (const uint4*)(g_Khp + (size_t)b * SS * 32);
    const uint4* Klg4 = (const uint4*)(g_Klp + (size_t)b * SS * 32);
    const uint4* Vhg4 = (const uint4*)(g_Vthp + (size_t)b * 64 * 1024);
    const uint4* Vlg4 = (const uint4*)(g_Vtlp + (size_t)b * 64 * 1024);

    const uint32_t KhS = sptr(Kh), KlS = sptr(Kl);
    const uint32_t VhS = sptr(Vth), VlS = sptr(Vtl);
    const uint32_t lrow = (lane & 7) * 144 + (lane >> 3) * 16;

    for (int kb = kb0; kb <= kb1; kb++) {
        #pragma unroll
        for (int i = 0; i < 4; i++) {
            int idx = tid + (i << 7);
            int r = idx >> 3, q = idx & 7;
            *(uint4*)&Kh[r * KPITCH + q * 8]  = Khg4[(size_t)(kb * 64 + r) * 8 + q];
            *(uint4*)&Kl[r * KPITCH + q * 8]  = Klg4[(size_t)(kb * 64 + r) * 8 + q];
            *(uint4*)&Vth[r * KPITCH + q * 8] = Vhg4[(size_t)r * 256 + kb * 8 + q];
            *(uint4*)&Vtl[r * KPITCH + q * 8] = Vlg4[(size_t)r * 256 + kb * 8 + q];
        }
        __syncthreads();

        // ---- S = Q K^T (3-term split), LDSM B-frags (4 kt per 2 LDSM.x4).
        float s[8][4] = {};
        #pragma unroll
        for (int nt = 0; nt < 8; nt++) {
            uint32_t ra = (uint32_t)(nt * 8 * 144) + lrow;
            uint32_t kh[8], kl[8];
            ldsm4(kh[0], kh[1], kh[2], kh[3], KhS + ra);
            ldsm4(kh[4], kh[5], kh[6], kh[7], KhS + ra + 64);
            ldsm4(kl[0], kl[1], kl[2], kl[3], KlS + ra);
            ldsm4(kl[4], kl[5], kl[6], kl[7], KlS + ra + 64);
            #pragma unroll
            for (int kt = 0; kt < 4; kt++) {
                mma_bf16(s[nt], qh[kt][0], qh[kt][1], qh[kt][2], qh[kt][3],
                         kh[2 * kt], kh[2 * kt + 1]);
                mma_bf16(s[nt], qh[kt][0], qh[kt][1], qh[kt][2], qh[kt][3],
                         kl[2 * kt], kl[2 * kt + 1]);
                mma_bf16(s[nt], ql[kt][0], ql[kt][1], ql[kt][2], ql[kt][3],
                         kh[2 * kt], kh[2 * kt + 1]);
            }
        }

        if (kb == qb) {
            #pragma unroll
            for (int nt = 0; nt < 8; nt++) {
                int kc = kb * 64 + nt * 8 + tg * 2;
                s[nt][0] = (kc     > qr0)     ? -1e30f : s[nt][0] * SCL;
                s[nt][1] = (kc + 1 > qr0)     ? -1e30f : s[nt][1] * SCL;
                s[nt][2] = (kc     > qr0 + 8) ? -1e30f : s[nt][2] * SCL;
                s[nt][3] = (kc + 1 > qr0 + 8) ? -1e30f : s[nt][3] * SCL;
            }
        } else {
            #pragma unroll
            for (int nt = 0; nt < 8; nt++) {
                s[nt][0] *= SCL; s[nt][1] *= SCL;
                s[nt][2] *= SCL; s[nt][3] *= SCL;
            }
        }

        float mx0 = -1e30f, mx1 = -1e30f;
        #pragma unroll
        for (int nt = 0; nt < 8; nt++) {
            mx0 = fmaxf(mx0, fmaxf(s[nt][0], s[nt][1]));
            mx1 = fmaxf(mx1, fmaxf(s[nt][2], s[nt][3]));
        }
        mx0 = fmaxf(mx0, __shfl_xor_sync(0xffffffffu, mx0, 1));
        mx0 = fmaxf(mx0, __shfl_xor_sync(0xffffffffu, mx0, 2));
        mx1 = fmaxf(mx1, __shfl_xor_sync(0xffffffffu, mx1, 1));
        mx1 = fmaxf(mx1, __shfl_xor_sync(0xffffffffu, mx1, 2));
        float nm0 = fmaxf(m0, mx0), nm1 = fmaxf(m1, mx1);
        float a0 = exp2_fast(m0 - nm0), a1 = exp2_fast(m1 - nm1);
        m0 = nm0; m1 = nm1;

        float rs0 = 0.0f, rs1 = 0.0f;
        #pragma unroll
        for (int nt = 0; nt < 8; nt++) {
            float p0 = exp2_fast(s[nt][0] - nm0);
            float p1 = exp2_fast(s[nt][1] - nm0);
            float p2 = exp2_fast(s[nt][2] - nm1);
            float p3 = exp2_fast(s[nt][3] - nm1);
            s[nt][0] = p0; s[nt][1] = p1; s[nt][2] = p2; s[nt][3] = p3;
            rs0 += p0 + p1;
            rs1 += p2 + p3;
        }
        rs0 += __shfl_xor_sync(0xffffffffu, rs0, 1);
        rs0 += __shfl_xor_sync(0xffffffffu, rs0, 2);
        rs1 += __shfl_xor_sync(0xffffffffu, rs1, 1);
        rs1 += __shfl_xor_sync(0xffffffffu, rs1, 2);
        l0 = l0 * a0 + rs0;
        l1 = l1 * a1 + rs1;
        #pragma unroll
        for (int nt = 0; nt < 8; nt++) {
            o[nt][0] *= a0; o[nt][1] *= a0;
            o[nt][2] *= a1; o[nt][3] *= a1;
        }

        // ---- Pre-split P fragments (A operands for PV).
        uint32_t ph[4][4], pl[4][4];
        #pragma unroll
        for (int kt = 0; kt < 4; kt++) {
            tsplit2(s[2 * kt][0],     s[2 * kt][1],     ph[kt][0], pl[kt][0]);
            tsplit2(s[2 * kt][2],     s[2 * kt][3],     ph[kt][1], pl[kt][1]);
            tsplit2(s[2 * kt + 1][0], s[2 * kt + 1][1], ph[kt][2], pl[kt][2]);
            tsplit2(s[2 * kt + 1][2], s[2 * kt + 1][3], ph[kt][3], pl[kt][3]);
        }

        // ---- O += P V (3-term split), LDSM V-frags, nt-outer.
        #pragma unroll
        for (int nt = 0; nt < 8; nt++) {
            uint32_t ra = (uint32_t)(nt * 8 * 144) + lrow;
            uint32_t vh[8], vl[8];
            ldsm4(vh[0], vh[1], vh[2], vh[3], VhS + ra);
            ldsm4(vh[4], vh[5], vh[6], vh[7], VhS + ra + 64);
            ldsm4(vl[0], vl[1], vl[2], vl[3], VlS + ra);
            ldsm4(vl[4], vl[5], vl[6], vl[7], VlS + ra + 64);
            #pragma unroll
            for (int kt = 0; kt < 4; kt++) {
                mma_bf16(o[nt], ph[kt][0], ph[kt][1], ph[kt][2], ph[kt][3],
                         vh[2 * kt], vh[2 * kt + 1]);
                mma_bf16(o[nt], ph[kt][0], ph[kt][1], ph[kt][2], ph[kt][3],
                         vl[2 * kt], vl[2 * kt + 1]);
                mma_bf16(o[nt], pl[kt][0], pl[kt][1], pl[kt][2], pl[kt][3],
                         vh[2 * kt], vh[2 * kt + 1]);
            }
        }
        __syncthreads();
    }

    const size_t unit = ((size_t)b * 32 + qb) * 4 + ci;
    float* pO = g_pO + unit * 4096 + (size_t)(wm * 16) * 64;
    #pragma unroll
    for (int nt = 0; nt < 8; nt++) {
        *(float2*)(pO + grow * 64 + nt * 8 + tg * 2) = make_float2(o[nt][0], o[nt][1]);
        *(float2*)(pO + (grow + 8) * 64 + nt * 8 + tg * 2) = make_float2(o[nt][2], o[nt][3]);
    }
    if (tg == 0) {
        g_pm[unit * 64 + wm * 16 + grow]     = m0;
        g_pm[unit * 64 + wm * 16 + grow + 8] = m1;
        g_pl[unit * 64 + wm * 16 + grow]     = l0;
        g_pl[unit * 64 + wm * 16 + grow + 8] = l1;
    }
}

// ---------------------------------------------------------------------------
// Kernel 2b: combine attention partials.
// ---------------------------------------------------------------------------
__global__ __launch_bounds__(256) void attn_combine(float* __restrict__ Out)
{
    const int qb = blockIdx.x;
    const int b  = blockIdx.y;
    const int tid = threadIdx.x;
    const int r = tid >> 2;
    const int c0 = (tid & 3) * 16;
    const int nc = (qb >> 3) + 1;

    const size_t ubase = ((size_t)b * 32 + qb) * 4;

    float mi[4], li[4];
    float M = -1e30f;
    #pragma unroll 4
    for (int i = 0; i < nc; i++) {
        mi[i] = g_pm[(ubase + i) * 64 + r];
        li[i] = g_pl[(ubase + i) * 64 + r];
        M = fmaxf(M, mi[i]);
    }

    float acc[16] = {};
    float L = 0.0f;
    #pragma unroll 4
    for (int i = 0; i < nc; i++) {
        float al = exp2_fast(mi[i] - M);
        L += al * li[i];
        const float* pO = g_pO + (ubase + i) * 4096 + (size_t)r * 64 + c0;
        #pragma unroll
        for (int q = 0; q < 4; q++) {
            float4 v = *(const float4*)(pO + q * 4);
            acc[q * 4 + 0] += al * v.x;
            acc[q * 4 + 1] += al * v.y;
            acc[q * 4 + 2] += al * v.z;
            acc[q * 4 + 3] += al * v.w;
        }
    }

    float inv = 1.0f / L;
    float* Og = Out + (size_t)(b * SS + qb * 64 + r) * HH + c0;
    #pragma unroll
    for (int q = 0; q < 4; q++) {
        *(float4*)(Og + q * 4) = make_float4(acc[q * 4 + 0] * inv, acc[q * 4 + 1] * inv,
                                             acc[q * 4 + 2] * inv, acc[q * 4 + 3] * inv);
    }
}

// ---------------------------------------------------------------------------
extern "C" void kernel_launch(void* const* d_in, const int* in_sizes, int n_in,
                              void* d_out, int out_size)
{
    const float* x  = (const float*)d_in[0];
    const float* Wq = (const float*)d_in[1];
    const float* Wk = (const float*)d_in[2];
    const float* Wv = (const float*)d_in[3];
    float* out = (float*)d_out;
    (void)in_sizes; (void)n_in; (void)out_size;

    cudaFuncSetAttribute(qkv_mma, cudaFuncAttributeMaxDynamicSharedMemorySize,
                         QKV_SMEM);

    prep_w<<<768, 256>>>(Wq, Wk, Wv);
    qkv_mma<<<(BB * SS) / 128, 256, QKV_SMEM>>>(x);
    prep_vt<<<dim3(SS / 64, BB), 256>>>();
    attn_part<<<dim3(80, BB), 128>>>(out);
    attn_combine<<<dim3(32, BB), 256>>>(out);
}

// round 15
// speedup vs baseline: 1.1913x; 1.0374x over previous
#include <cuda_runtime.h>
#include <cuda_bf16.h>
#include <math.h>
#include <stdint.h>

#define BB 8
#define SS 2048
#define DD 1024
#define HH 64

// Scratch.
__device__ float g_Q[BB * SS * HH];                 // fp32 Q
__device__ float g_V[BB * SS * HH];                 // fp32 V (input to prep_vt)
__device__ uint32_t g_Khp[BB * SS * 32];            // K hi, bf16x2 pairs along h
__device__ uint32_t g_Klp[BB * SS * 32];            // K lo
__device__ uint32_t g_Vthp[BB * 64 * 1024];         // V^T hi: [b][h][s/2] pairs along s
__device__ uint32_t g_Vtlp[BB * 64 * 1024];         // V^T lo
__device__ __nv_bfloat16 g_Bh[192 * 1024];          // weights hi  [n][k]
__device__ __nv_bfloat16 g_Bl[192 * 1024];          // weights lo

// Split-K attention partials.
__device__ float g_pO[BB * 32 * 4 * 64 * 64];       // 16.8 MB
__device__ float g_pm[BB * 32 * 4 * 64];
__device__ float g_pl[BB * 32 * 4 * 64];

// ---------------------------------------------------------------------------
__device__ __forceinline__ void tsplit2(float a, float b, uint32_t& hi, uint32_t& lo) {
    uint32_t ia = __float_as_uint(a), ib = __float_as_uint(b);
    hi = __byte_perm(ia, ib, 0x7632);
    float ra = a - __uint_as_float(ia & 0xFFFF0000u);
    float rb = b - __uint_as_float(ib & 0xFFFF0000u);
    asm("cvt.rn.bf16x2.f32 %0, %1, %2;" : "=r"(lo) : "f"(rb), "f"(ra));
}

__device__ __forceinline__ float exp2_fast(float x) {
    x = fmaxf(x, -80.0f);
    float z = x + 12582912.0f;
    float n = z - 12582912.0f;
    float f = x - n;
    float p =            1.3333558e-3f;
    p = fmaf(p, f, 9.6181291e-3f);
    p = fmaf(p, f, 5.5504109e-2f);
    p = fmaf(p, f, 2.4022650e-1f);
    p = fmaf(p, f, 6.9314718e-1f);
    p = fmaf(p, f, 1.0f);
    int e = __float_as_int(z);
    float sc = __int_as_float((e + (127 - 0x4B400000)) << 23);
    return p * sc;
}

__device__ __forceinline__ void mma_bf16(float c[4],
                                         uint32_t a0, uint32_t a1, uint32_t a2, uint32_t a3,
                                         uint32_t b0, uint32_t b1) {
    asm volatile(
        "mma.sync.aligned.m16n8k16.row.col.f32.bf16.bf16.f32 "
        "{%0,%1,%2,%3}, {%4,%5,%6,%7}, {%8,%9}, {%0,%1,%2,%3};"
        : "+f"(c[0]), "+f"(c[1]), "+f"(c[2]), "+f"(c[3])
        : "r"(a0), "r"(a1), "r"(a2), "r"(a3), "r"(b0), "r"(b1));
}

__device__ __forceinline__ void ldsm4(uint32_t& r0, uint32_t& r1,
                                      uint32_t& r2, uint32_t& r3, uint32_t saddr) {
    asm volatile("ldmatrix.sync.aligned.m8n8.x4.shared.b16 {%0,%1,%2,%3}, [%4];"
        : "=r"(r0), "=r"(r1), "=r"(r2), "=r"(r3) : "r"(saddr));
}

__device__ __forceinline__ uint32_t sptr(const void* p) {
    return (uint32_t)__cvta_generic_to_shared(p);
}

__device__ __forceinline__ uint32_t lds32(const __nv_bfloat16* p) {
    return *(const uint32_t*)p;
}

// ---------------------------------------------------------------------------
// Kernel 0: split weights.
// ---------------------------------------------------------------------------
__global__ void prep_w(const float* __restrict__ Wq,
                       const float* __restrict__ Wk,
                       const float* __restrict__ Wv)
{
    int i = blockIdx.x * blockDim.x + threadIdx.x;
    int n = i >> 10;
    int k = i & 1023;
    int m = n >> 6;
    int col = n & 63;
    const float* W = (m == 0) ? Wq : (m == 1) ? Wk : Wv;
    float w = W[k * 64 + col];
    __nv_bfloat16 h = __float2bfloat16(w);
    float lo = w - __bfloat162float(h);
    g_Bh[(size_t)n * 1024 + k] = h;
    g_Bl[(size_t)n * 1024 + k] = __float2bfloat16(lo);
}

// ---------------------------------------------------------------------------
// Kernel 1: QKV projection, double-buffered + A-prefetch + LDSM fragments.
// (R14 version — measured winner, ~61us.)
// ---------------------------------------------------------------------------
#define APITCH 40
#define QA_OFF  0
#define QAL_OFF 10240
#define QB_OFF  20480
#define QBL_OFF 35840
#define QSTAGE  51200
#define QKV_SMEM (2 * QSTAGE)

__global__ __launch_bounds__(256) void qkv_mma(const float* __restrict__ x)
{
    extern __shared__ __align__(16) char qsm[];

    const int tid = threadIdx.x;
    const int wid = tid >> 5;
    const int lane = tid & 31;
    const int grow = lane >> 2;
    const int tg = lane & 3;
    const int warp_m = wid & 3;
    const int warp_n = wid >> 2;
    const int row0 = blockIdx.x * 128;

    const uint32_t alrow = (lane & 15) * 80 + (lane >> 4) * 16;
    const uint32_t blrow = ((lane & 7) + (lane >> 4) * 8) * 80 + ((lane >> 3) & 1) * 16;

    int ar[4], ac[4];
    #pragma unroll
    for (int i = 0; i < 4; i++) {
        int idx = tid + (i << 8);
        ar[i] = idx >> 3;
        ac[i] = (idx & 7) * 4;
    }
    int br[3], bq[3];
    #pragma unroll
    for (int i = 0; i < 3; i++) {
        int idx = tid + (i << 8);
        br[i] = idx >> 2;
        bq[i] = idx & 3;
    }

    float acc[2][12][4] = {};
    float4 fA[4];

    auto store_chunk = [&](char* st, int k0) {
        #pragma unroll
        for (int i = 0; i < 4; i++) {
            uint32_t h01, l01, h23, l23;
            tsplit2(fA[i].x, fA[i].y, h01, l01);
            tsplit2(fA[i].z, fA[i].w, h23, l23);
            int off = ar[i] * 80 + ac[i] * 2;
            *(uint2*)(st + QA_OFF + off)  = make_uint2(h01, h23);
            *(uint2*)(st + QAL_OFF + off) = make_uint2(l01, l23);
        }
        #pragma unroll
        for (int i = 0; i < 3; i++) {
            uint4 vh = *(const uint4*)(g_Bh + (size_t)br[i] * 1024 + k0 + bq[i] * 8);
            uint4 vl = *(const uint4*)(g_Bl + (size_t)br[i] * 1024 + k0 + bq[i] * 8);
            int off = br[i] * 80 + bq[i] * 16;
            *(uint4*)(st + QB_OFF + off)  = vh;
            *(uint4*)(st + QBL_OFF + off) = vl;
        }
    };

    #pragma unroll
    for (int i = 0; i < 4; i++)
        fA[i] = *(const float4*)(x + (size_t)(row0 + ar[i]) * DD + ac[i]);
    store_chunk(qsm, 0);
    __syncthreads();

    for (int c = 0; c < 32; c++) {
        const int k1 = (c + 1) * 32;
        if (k1 < DD) {
            #pragma unroll
            for (int i = 0; i < 4; i++)
                fA[i] = *(const float4*)(x + (size_t)(row0 + ar[i]) * DD + k1 + ac[i]);
        }

        char* cur = qsm + (c & 1) * QSTAGE;
        const uint32_t AhS = sptr(cur + QA_OFF);
        const uint32_t AlS = sptr(cur + QAL_OFF);
        const uint32_t BhS = sptr(cur + QB_OFF);
        const uint32_t BlS = sptr(cur + QBL_OFF);

        #pragma unroll
        for (int ks = 0; ks < 2; ks++) {
            uint32_t ah[2][4], al[2][4];
            #pragma unroll
            for (int mt = 0; mt < 2; mt++) {
                uint32_t ra = (warp_m * 32 + mt * 16) * 80 + alrow + ks * 32;
                ldsm4(ah[mt][0], ah[mt][1], ah[mt][2], ah[mt][3], AhS + ra);
                ldsm4(al[mt][0], al[mt][1], al[mt][2], al[mt][3], AlS + ra);
            }
            #pragma unroll
            for (int p = 0; p < 6; p++) {
                uint32_t rb = (warp_n * 96 + p * 16) * 80 + blrow + ks * 32;
                uint32_t bh[4], bl[4];
                ldsm4(bh[0], bh[1], bh[2], bh[3], BhS + rb);
                ldsm4(bl[0], bl[1], bl[2], bl[3], BlS + rb);
                #pragma unroll
                for (int j = 0; j < 2; j++) {
                    int nt = 2 * p + j;
                    #pragma unroll
                    for (int mt = 0; mt < 2; mt++) {
                        mma_bf16(acc[mt][nt], ah[mt][0], ah[mt][1], ah[mt][2], ah[mt][3],
                                 bh[2 * j], bh[2 * j + 1]);
                        mma_bf16(acc[mt][nt], ah[mt][0], ah[mt][1], ah[mt][2], ah[mt][3],
                                 bl[2 * j], bl[2 * j + 1]);
                        mma_bf16(acc[mt][nt], al[mt][0], al[mt][1], al[mt][2], al[mt][3],
                                 bh[2 * j], bh[2 * j + 1]);
                    }
                }
            }
        }

        if (k1 < DD) store_chunk(qsm + ((c + 1) & 1) * QSTAGE, k1);
        __syncthreads();
    }

    #pragma unroll
    for (int mt = 0; mt < 2; mt++) {
        int r = row0 + warp_m * 32 + mt * 16 + grow;
        #pragma unroll
        for (int nt = 0; nt < 12; nt++) {
            int col = warp_n * 96 + nt * 8 + tg * 2;
            int mat = col >> 6;
            int c = col & 63;
            if (mat == 1) {
                uint32_t h0, l0, h1, l1;
                tsplit2(acc[mt][nt][0], acc[mt][nt][1], h0, l0);
                tsplit2(acc[mt][nt][2], acc[mt][nt][3], h1, l1);
                int pidx = c >> 1;
                g_Khp[(size_t)r * 32 + pidx] = h0;
                g_Klp[(size_t)r * 32 + pidx] = l0;
                g_Khp[(size_t)(r + 8) * 32 + pidx] = h1;
                g_Klp[(size_t)(r + 8) * 32 + pidx] = l1;
            } else {
                float* dst = (mat == 0) ? g_Q : g_V;
                *(float2*)(dst + (size_t)r * 64 + c) =
                    make_float2(acc[mt][nt][0], acc[mt][nt][1]);
                *(float2*)(dst + (size_t)(r + 8) * 64 + c) =
                    make_float2(acc[mt][nt][2], acc[mt][nt][3]);
            }
        }
    }
}

// ---------------------------------------------------------------------------
// Kernel 1b: transpose + split V once.
// ---------------------------------------------------------------------------
__global__ __launch_bounds__(256) void prep_vt()
{
    __shared__ float vt[64 * 65];
    const int tid = threadIdx.x;
    const int s0 = blockIdx.x * 64;
    const int b  = blockIdx.y;

    #pragma unroll
    for (int i = 0; i < 4; i++) {
        int idx = tid + (i << 8);
        int r = idx >> 4;
        int c4 = (idx & 15) << 2;
        float4 f = *(const float4*)(g_V + (size_t)(b * SS + s0 + r) * 64 + c4);
        vt[r * 65 + c4 + 0] = f.x;  vt[r * 65 + c4 + 1] = f.y;
        vt[r * 65 + c4 + 2] = f.z;  vt[r * 65 + c4 + 3] = f.w;
    }
    __syncthreads();

    #pragma unroll
    for (int i = 0; i < 8; i++) {
        int idx = tid + (i << 8);
        int h  = idx >> 5;
        int sp = idx & 31;
        float v0 = vt[(sp * 2 + 0) * 65 + h];
        float v1 = vt[(sp * 2 + 1) * 65 + h];
        uint32_t hi, lo;
        tsplit2(v0, v1, hi, lo);
        size_t o = (size_t)(b * 64 + h) * 1024 + (s0 >> 1) + sp;
        g_Vthp[o] = hi;
        g_Vtlp[o] = lo;
    }
}

// ---------------------------------------------------------------------------
// Kernel 2a: split-K flash attention partials (R13 scalar-LDS version —
// measured 56-57us across three rounds; LDSM variant regressed to 65).
// ---------------------------------------------------------------------------
#define KPITCH 72
#define SCL 0.18033688011112042f   /* 0.125 * log2(e) */

__global__ __launch_bounds__(128) void attn_part(float* __restrict__ dummy)
{
    __shared__ __align__(16) __nv_bfloat16 Kh[64 * KPITCH];
    __shared__ __align__(16) __nv_bfloat16 Kl[64 * KPITCH];
    __shared__ __align__(16) __nv_bfloat16 Vth[64 * KPITCH];
    __shared__ __align__(16) __nv_bfloat16 Vtl[64 * KPITCH];
    (void)dummy;

    const int tid = threadIdx.x;
    const int wm = tid >> 5;
    const int lane = tid & 31;
    const int grow = lane >> 2;
    const int tg = lane & 3;
    const int u = blockIdx.x;
    const int b = blockIdx.y;

    int qb, ci;
    if (u < 8)       { qb = u;                 ci = 0; }
    else if (u < 24) { qb = 8  + ((u - 8) >> 1);  ci = (u - 8) & 1; }
    else if (u < 48) { qb = 16 + (u - 24) / 3;    ci = (u - 24) % 3; }
    else             { qb = 24 + ((u - 48) >> 2); ci = (u - 48) & 3; }

    const int kb0 = ci * 8;
    const int kb1 = min(kb0 + 7, qb);

    const float* Qg = g_Q + (size_t)(b * SS + qb * 64 + wm * 16) * HH;

    uint32_t qh[4][4], ql[4][4];
    #pragma unroll
    for (int kt = 0; kt < 4; kt++) {
        float2 v00 = *(const float2*)(Qg + grow * HH + kt * 16 + tg * 2);
        float2 v10 = *(const float2*)(Qg + (grow + 8) * HH + kt * 16 + tg * 2);
        float2 v01 = *(const float2*)(Qg + grow * HH + kt * 16 + tg * 2 + 8);
        float2 v11 = *(const float2*)(Qg + (grow + 8) * HH + kt * 16 + tg * 2 + 8);
        tsplit2(v00.x, v00.y, qh[kt][0], ql[kt][0]);
        tsplit2(v10.x, v10.y, qh[kt][1], ql[kt][1]);
        tsplit2(v01.x, v01.y, qh[kt][2], ql[kt][2]);
        tsplit2(v11.x, v11.y, qh[kt][3], ql[kt][3]);
    }

    float o[8][4] = {};
    float m0 = -1e30f, m1 = -1e30f, l0 = 0.0f, l1 = 0.0f;
    const int qr0 = qb * 64 + wm * 16 + grow;

    const uint4* Khg4 = (const uint4*)(g_Khp + (size_t)b * SS * 32);
    const uint4* Klg4 = (const uint4*)(g_Klp + (size_t)b * SS * 32);
    const uint4* Vhg4 = (const uint4*)(g_Vthp + (size_t)b * 64 * 1024);
    const uint4* Vlg4 = (const uint4*)(g_Vtlp + (size_t)b * 64 * 1024);

    for (int kb = kb0; kb <= kb1; kb++) {
        #pragma unroll
        for (int i = 0; i < 4; i++) {
            int idx = tid + (i << 7);
            int r = idx >> 3, q = idx & 7;
            *(uint4*)&Kh[r * KPITCH + q * 8]  = Khg4[(size_t)(kb * 64 + r) * 8 + q];
            *(uint4*)&Kl[r * KPITCH + q * 8]  = Klg4[(size_t)(kb * 64 + r) * 8 + q];
            *(uint4*)&Vth[r * KPITCH + q * 8] = Vhg4[(size_t)r * 256 + kb * 8 + q];
            *(uint4*)&Vtl[r * KPITCH + q * 8] = Vlg4[(size_t)r * 256 + kb * 8 + q];
        }
        __syncthreads();

        float s[8][4] = {};
        #pragma unroll
        for (int nt = 0; nt < 8; nt++) {
            #pragma unroll
            for (int kt = 0; kt < 4; kt++) {
                int cb = (nt * 8 + grow) * KPITCH + kt * 16 + tg * 2;
                uint32_t bh0 = lds32(Kh + cb), bh1 = lds32(Kh + cb + 8);
                uint32_t bl0 = lds32(Kl + cb), bl1 = lds32(Kl + cb + 8);
                mma_bf16(s[nt], qh[kt][0], qh[kt][1], qh[kt][2], qh[kt][3], bh0, bh1);
                mma_bf16(s[nt], qh[kt][0], qh[kt][1], qh[kt][2], qh[kt][3], bl0, bl1);
                mma_bf16(s[nt], ql[kt][0], ql[kt][1], ql[kt][2], ql[kt][3], bh0, bh1);
            }
        }

        if (kb == qb) {
            #pragma unroll
            for (int nt = 0; nt < 8; nt++) {
                int kc = kb * 64 + nt * 8 + tg * 2;
                s[nt][0] = (kc     > qr0)     ? -1e30f : s[nt][0] * SCL;
                s[nt][1] = (kc + 1 > qr0)     ? -1e30f : s[nt][1] * SCL;
                s[nt][2] = (kc     > qr0 + 8) ? -1e30f : s[nt][2] * SCL;
                s[nt][3] = (kc + 1 > qr0 + 8) ? -1e30f : s[nt][3] * SCL;
            }
        } else {
            #pragma unroll
            for (int nt = 0; nt < 8; nt++) {
                s[nt][0] *= SCL; s[nt][1] *= SCL;
                s[nt][2] *= SCL; s[nt][3] *= SCL;
            }
        }

        float mx0 = -1e30f, mx1 = -1e30f;
        #pragma unroll
        for (int nt = 0; nt < 8; nt++) {
            mx0 = fmaxf(mx0, fmaxf(s[nt][0], s[nt][1]));
            mx1 = fmaxf(mx1, fmaxf(s[nt][2], s[nt][3]));
        }
        mx0 = fmaxf(mx0, __shfl_xor_sync(0xffffffffu, mx0, 1));
        mx0 = fmaxf(mx0, __shfl_xor_sync(0xffffffffu, mx0, 2));
        mx1 = fmaxf(mx1, __shfl_xor_sync(0xffffffffu, mx1, 1));
        mx1 = fmaxf(mx1, __shfl_xor_sync(0xffffffffu, mx1, 2));
        float nm0 = fmaxf(m0, mx0), nm1 = fmaxf(m1, mx1);
        float a0 = exp2_fast(m0 - nm0), a1 = exp2_fast(m1 - nm1);
        m0 = nm0; m1 = nm1;

        float rs0 = 0.0f, rs1 = 0.0f;
        #pragma unroll
        for (int nt = 0; nt < 8; nt++) {
            float p0 = exp2_fast(s[nt][0] - nm0);
            float p1 = exp2_fast(s[nt][1] - nm0);
            float p2 = exp2_fast(s[nt][2] - nm1);
            float p3 = exp2_fast(s[nt][3] - nm1);
            s[nt][0] = p0; s[nt][1] = p1; s[nt][2] = p2; s[nt][3] = p3;
            rs0 += p0 + p1;
            rs1 += p2 + p3;
        }
        rs0 += __shfl_xor_sync(0xffffffffu, rs0, 1);
        rs0 += __shfl_xor_sync(0xffffffffu, rs0, 2);
        rs1 += __shfl_xor_sync(0xffffffffu, rs1, 1);
        rs1 += __shfl_xor_sync(0xffffffffu, rs1, 2);
        l0 = l0 * a0 + rs0;
        l1 = l1 * a1 + rs1;
        #pragma unroll
        for (int nt = 0; nt < 8; nt++) {
            o[nt][0] *= a0; o[nt][1] *= a0;
            o[nt][2] *= a1; o[nt][3] *= a1;
        }

        #pragma unroll
        for (int kt = 0; kt < 4; kt++) {
            uint32_t ph[4], pl[4];
            tsplit2(s[2 * kt][0],     s[2 * kt][1],     ph[0], pl[0]);
            tsplit2(s[2 * kt][2],     s[2 * kt][3],     ph[1], pl[1]);
            tsplit2(s[2 * kt + 1][0], s[2 * kt + 1][1], ph[2], pl[2]);
            tsplit2(s[2 * kt + 1][2], s[2 * kt + 1][3], ph[3], pl[3]);
            #pragma unroll
            for (int nt = 0; nt < 8; nt++) {
                int cb = (nt * 8 + grow) * KPITCH + kt * 16 + tg * 2;
                uint32_t bh0 = lds32(Vth + cb), bh1 = lds32(Vth + cb + 8);
                uint32_t bl0 = lds32(Vtl + cb), bl1 = lds32(Vtl + cb + 8);
                mma_bf16(o[nt], ph[0], ph[1], ph[2], ph[3], bh0, bh1);
                mma_bf16(o[nt], ph[0], ph[1], ph[2], ph[3], bl0, bl1);
                mma_bf16(o[nt], pl[0], pl[1], pl[2], pl[3], bh0, bh1);
            }
        }
        __syncthreads();
    }

    const size_t unit = ((size_t)b * 32 + qb) * 4 + ci;
    float* pO = g_pO + unit * 4096 + (size_t)(wm * 16) * 64;
    #pragma unroll
    for (int nt = 0; nt < 8; nt++) {
        *(float2*)(pO + grow * 64 + nt * 8 + tg * 2) = make_float2(o[nt][0], o[nt][1]);
        *(float2*)(pO + (grow + 8) * 64 + nt * 8 + tg * 2) = make_float2(o[nt][2], o[nt][3]);
    }
    if (tg == 0) {
        g_pm[unit * 64 + wm * 16 + grow]     = m0;
        g_pm[unit * 64 + wm * 16 + grow + 8] = m1;
        g_pl[unit * 64 + wm * 16 + grow]     = l0;
        g_pl[unit * 64 + wm * 16 + grow + 8] = l1;
    }
}

// ---------------------------------------------------------------------------
// Kernel 2b: combine attention partials.
// ---------------------------------------------------------------------------
__global__ __launch_bounds__(256) void attn_combine(float* __restrict__ Out)
{
    const int qb = blockIdx.x;
    const int b  = blockIdx.y;
    const int tid = threadIdx.x;
    const int r = tid >> 2;
    const int c0 = (tid & 3) * 16;
    const int nc = (qb >> 3) + 1;

    const size_t ubase = ((size_t)b * 32 + qb) * 4;

    float mi[4], li[4];
    float M = -1e30f;
    #pragma unroll 4
    for (int i = 0; i < nc; i++) {
        mi[i] = g_pm[(ubase + i) * 64 + r];
        li[i] = g_pl[(ubase + i) * 64 + r];
        M = fmaxf(M, mi[i]);
    }

    float acc[16] = {};
    float L = 0.0f;
    #pragma unroll 4
    for (int i = 0; i < nc; i++) {
        float al = exp2_fast(mi[i] - M);
        L += al * li[i];
        const float* pO = g_pO + (ubase + i) * 4096 + (size_t)r * 64 + c0;
        #pragma unroll
        for (int q = 0; q < 4; q++) {
            float4 v = *(const float4*)(pO + q * 4);
            acc[q * 4 + 0] += al * v.x;
            acc[q * 4 + 1] += al * v.y;
            acc[q * 4 + 2] += al * v.z;
            acc[q * 4 + 3] += al * v.w;
        }
    }

    float inv = 1.0f / L;
    float* Og = Out + (size_t)(b * SS + qb * 64 + r) * HH + c0;
    #pragma unroll
    for (int q = 0; q < 4; q++) {
        *(float4*)(Og + q * 4) = make_float4(acc[q * 4 + 0] * inv, acc[q * 4 + 1] * inv,
                                             acc[q * 4 + 2] * inv, acc[q * 4 + 3] * inv);
    }
}

// ---------------------------------------------------------------------------
extern "C" void kernel_launch(void* const* d_in, const int* in_sizes, int n_in,
                              void* d_out, int out_size)
{
    const float* x  = (const float*)d_in[0];
    const float* Wq = (const float*)d_in[1];
    const float* Wk = (const float*)d_in[2];
    const float* Wv = (const float*)d_in[3];
    float* out = (float*)d_out;
    (void)in_sizes; (void)n_in; (void)out_size;

    cudaFuncSetAttribute(qkv_mma, cudaFuncAttributeMaxDynamicSharedMemorySize,
                         QKV_SMEM);

    prep_w<<<768, 256>>>(Wq, Wk, Wv);
    qkv_mma<<<(BB * SS) / 128, 256, QKV_SMEM>>>(x);
    prep_vt<<<dim3(SS / 64, BB), 256>>>();
    attn_part<<<dim3(80, BB), 128>>>(out);
    attn_combine<<<dim3(32, BB), 256>>>(out);
}

// round 16
// speedup vs baseline: 1.3013x; 1.0923x over previous
#include <cuda_runtime.h>
#include <cuda_bf16.h>
#include <math.h>
#include <stdint.h>

#define BB 8
#define SS 2048
#define DD 1024
#define HH 64

// Scratch.
__device__ float g_Q[BB * SS * HH];                 // fp32 Q
__device__ uint32_t g_Khp[BB * SS * 32];            // K hi, bf16x2 pairs along h
__device__ uint32_t g_Klp[BB * SS * 32];            // K lo
__device__ uint32_t g_Vthp[BB * 64 * 1024];         // V^T hi: [b][h][s/2] pairs along s
__device__ uint32_t g_Vtlp[BB * 64 * 1024];         // V^T lo
__device__ __nv_bfloat16 g_Bh[192 * 1024];          // weights hi  [n][k]
__device__ __nv_bfloat16 g_Bl[192 * 1024];          // weights lo

// Split-K attention partials.
__device__ float g_pO[BB * 32 * 4 * 64 * 64];       // 16.8 MB
__device__ float g_pm[BB * 32 * 4 * 64];
__device__ float g_pl[BB * 32 * 4 * 64];

// ---------------------------------------------------------------------------
__device__ __forceinline__ void tsplit2(float a, float b, uint32_t& hi, uint32_t& lo) {
    uint32_t ia = __float_as_uint(a), ib = __float_as_uint(b);
    hi = __byte_perm(ia, ib, 0x7632);
    float ra = a - __uint_as_float(ia & 0xFFFF0000u);
    float rb = b - __uint_as_float(ib & 0xFFFF0000u);
    asm("cvt.rn.bf16x2.f32 %0, %1, %2;" : "=r"(lo) : "f"(rb), "f"(ra));
}

__device__ __forceinline__ float exp2_fast(float x) {
    x = fmaxf(x, -80.0f);
    float z = x + 12582912.0f;
    float n = z - 12582912.0f;
    float f = x - n;
    float p =            1.3333558e-3f;
    p = fmaf(p, f, 9.6181291e-3f);
    p = fmaf(p, f, 5.5504109e-2f);
    p = fmaf(p, f, 2.4022650e-1f);
    p = fmaf(p, f, 6.9314718e-1f);
    p = fmaf(p, f, 1.0f);
    int e = __float_as_int(z);
    float sc = __int_as_float((e + (127 - 0x4B400000)) << 23);
    return p * sc;
}

__device__ __forceinline__ void mma_bf16(float c[4],
                                         uint32_t a0, uint32_t a1, uint32_t a2, uint32_t a3,
                                         uint32_t b0, uint32_t b1) {
    asm volatile(
        "mma.sync.aligned.m16n8k16.row.col.f32.bf16.bf16.f32 "
        "{%0,%1,%2,%3}, {%4,%5,%6,%7}, {%8,%9}, {%0,%1,%2,%3};"
        : "+f"(c[0]), "+f"(c[1]), "+f"(c[2]), "+f"(c[3])
        : "r"(a0), "r"(a1), "r"(a2), "r"(a3), "r"(b0), "r"(b1));
}

__device__ __forceinline__ void ldsm4(uint32_t& r0, uint32_t& r1,
                                      uint32_t& r2, uint32_t& r3, uint32_t saddr) {
    asm volatile("ldmatrix.sync.aligned.m8n8.x4.shared.b16 {%0,%1,%2,%3}, [%4];"
        : "=r"(r0), "=r"(r1), "=r"(r2), "=r"(r3) : "r"(saddr));
}

__device__ __forceinline__ void ldsm2(uint32_t& r0, uint32_t& r1, uint32_t saddr) {
    asm volatile("ldmatrix.sync.aligned.m8n8.x2.shared.b16 {%0,%1}, [%2];"
        : "=r"(r0), "=r"(r1) : "r"(saddr));
}

__device__ __forceinline__ uint32_t sptr(const void* p) {
    return (uint32_t)__cvta_generic_to_shared(p);
}

// ---------------------------------------------------------------------------
// Kernel 0: split weights.
// ---------------------------------------------------------------------------
__global__ void prep_w(const float* __restrict__ Wq,
                       const float* __restrict__ Wk,
                       const float* __restrict__ Wv)
{
    int i = blockIdx.x * blockDim.x + threadIdx.x;
    int n = i >> 10;
    int k = i & 1023;
    int m = n >> 6;
    int col = n & 63;
    const float* W = (m == 0) ? Wq : (m == 1) ? Wk : Wv;
    float w = W[k * 64 + col];
    __nv_bfloat16 h = __float2bfloat16(w);
    float lo = w - __bfloat162float(h);
    g_Bh[(size_t)n * 1024 + k] = h;
    g_Bl[(size_t)n * 1024 + k] = __float2bfloat16(lo);
}

// ---------------------------------------------------------------------------
// Kernel 1: QKV projection, double-buffered + A-prefetch + LDSM fragments
// (R14 winner), with V transpose+split folded into the epilogue (smem reuse).
// ---------------------------------------------------------------------------
#define APITCH 40
#define QA_OFF  0
#define QAL_OFF 10240
#define QB_OFF  20480
#define QBL_OFF 35840
#define QSTAGE  51200
#define QKV_SMEM (2 * QSTAGE)

__global__ __launch_bounds__(256) void qkv_mma(const float* __restrict__ x)
{
    extern __shared__ __align__(16) char qsm[];

    const int tid = threadIdx.x;
    const int wid = tid >> 5;
    const int lane = tid & 31;
    const int grow = lane >> 2;
    const int tg = lane & 3;
    const int warp_m = wid & 3;
    const int warp_n = wid >> 2;
    const int row0 = blockIdx.x * 128;

    const uint32_t alrow = (lane & 15) * 80 + (lane >> 4) * 16;
    const uint32_t blrow = ((lane & 7) + (lane >> 4) * 8) * 80 + ((lane >> 3) & 1) * 16;

    int ar[4], ac[4];
    #pragma unroll
    for (int i = 0; i < 4; i++) {
        int idx = tid + (i << 8);
        ar[i] = idx >> 3;
        ac[i] = (idx & 7) * 4;
    }
    int br[3], bq[3];
    #pragma unroll
    for (int i = 0; i < 3; i++) {
        int idx = tid + (i << 8);
        br[i] = idx >> 2;
        bq[i] = idx & 3;
    }

    float acc[2][12][4] = {};
    float4 fA[4];

    auto store_chunk = [&](char* st, int k0) {
        #pragma unroll
        for (int i = 0; i < 4; i++) {
            uint32_t h01, l01, h23, l23;
            tsplit2(fA[i].x, fA[i].y, h01, l01);
            tsplit2(fA[i].z, fA[i].w, h23, l23);
            int off = ar[i] * 80 + ac[i] * 2;
            *(uint2*)(st + QA_OFF + off)  = make_uint2(h01, h23);
            *(uint2*)(st + QAL_OFF + off) = make_uint2(l01, l23);
        }
        #pragma unroll
        for (int i = 0; i < 3; i++) {
            uint4 vh = *(const uint4*)(g_Bh + (size_t)br[i] * 1024 + k0 + bq[i] * 8);
            uint4 vl = *(const uint4*)(g_Bl + (size_t)br[i] * 1024 + k0 + bq[i] * 8);
            int off = br[i] * 80 + bq[i] * 16;
            *(uint4*)(st + QB_OFF + off)  = vh;
            *(uint4*)(st + QBL_OFF + off) = vl;
        }
    };

    #pragma unroll
    for (int i = 0; i < 4; i++)
        fA[i] = *(const float4*)(x + (size_t)(row0 + ar[i]) * DD + ac[i]);
    store_chunk(qsm, 0);
    __syncthreads();

    for (int c = 0; c < 32; c++) {
        const int k1 = (c + 1) * 32;
        if (k1 < DD) {
            #pragma unroll
            for (int i = 0; i < 4; i++)
                fA[i] = *(const float4*)(x + (size_t)(row0 + ar[i]) * DD + k1 + ac[i]);
        }

        char* cur = qsm + (c & 1) * QSTAGE;
        const uint32_t AhS = sptr(cur + QA_OFF);
        const uint32_t AlS = sptr(cur + QAL_OFF);
        const uint32_t BhS = sptr(cur + QB_OFF);
        const uint32_t BlS = sptr(cur + QBL_OFF);

        #pragma unroll
        for (int ks = 0; ks < 2; ks++) {
            uint32_t ah[2][4], al[2][4];
            #pragma unroll
            for (int mt = 0; mt < 2; mt++) {
                uint32_t ra = (warp_m * 32 + mt * 16) * 80 + alrow + ks * 32;
                ldsm4(ah[mt][0], ah[mt][1], ah[mt][2], ah[mt][3], AhS + ra);
                ldsm4(al[mt][0], al[mt][1], al[mt][2], al[mt][3], AlS + ra);
            }
            #pragma unroll
            for (int p = 0; p < 6; p++) {
                uint32_t rb = (warp_n * 96 + p * 16) * 80 + blrow + ks * 32;
                uint32_t bh[4], bl[4];
                ldsm4(bh[0], bh[1], bh[2], bh[3], BhS + rb);
                ldsm4(bl[0], bl[1], bl[2], bl[3], BlS + rb);
                #pragma unroll
                for (int j = 0; j < 2; j++) {
                    int nt = 2 * p + j;
                    #pragma unroll
                    for (int mt = 0; mt < 2; mt++) {
                        mma_bf16(acc[mt][nt], ah[mt][0], ah[mt][1], ah[mt][2], ah[mt][3],
                                 bh[2 * j], bh[2 * j + 1]);
                        mma_bf16(acc[mt][nt], ah[mt][0], ah[mt][1], ah[mt][2], ah[mt][3],
                                 bl[2 * j], bl[2 * j + 1]);
                        mma_bf16(acc[mt][nt], al[mt][0], al[mt][1], al[mt][2], al[mt][3],
                                 bh[2 * j], bh[2 * j + 1]);
                    }
                }
            }
        }

        if (k1 < DD) store_chunk(qsm + ((c + 1) & 1) * QSTAGE, k1);
        __syncthreads();
    }

    // ---- Epilogue. Q fp32; K split; V -> smem (reuse qsm) for transpose.
    float* vbuf = (float*)qsm;              // [128][65] fp32 = 33 KB
    #pragma unroll
    for (int mt = 0; mt < 2; mt++) {
        int rl = warp_m * 32 + mt * 16 + grow;
        int r = row0 + rl;
        #pragma unroll
        for (int nt = 0; nt < 12; nt++) {
            int col = warp_n * 96 + nt * 8 + tg * 2;
            int mat = col >> 6;
            int c = col & 63;
            if (mat == 1) {
                uint32_t h0, l0, h1, l1;
                tsplit2(acc[mt][nt][0], acc[mt][nt][1], h0, l0);
                tsplit2(acc[mt][nt][2], acc[mt][nt][3], h1, l1);
                int pidx = c >> 1;
                g_Khp[(size_t)r * 32 + pidx] = h0;
                g_Klp[(size_t)r * 32 + pidx] = l0;
                g_Khp[(size_t)(r + 8) * 32 + pidx] = h1;
                g_Klp[(size_t)(r + 8) * 32 + pidx] = l1;
            } else if (mat == 0) {
                *(float2*)(g_Q + (size_t)r * 64 + c) =
                    make_float2(acc[mt][nt][0], acc[mt][nt][1]);
                *(float2*)(g_Q + (size_t)(r + 8) * 64 + c) =
                    make_float2(acc[mt][nt][2], acc[mt][nt][3]);
            } else {
                vbuf[rl * 65 + c]           = acc[mt][nt][0];
                vbuf[rl * 65 + c + 1]       = acc[mt][nt][1];
                vbuf[(rl + 8) * 65 + c]     = acc[mt][nt][2];
                vbuf[(rl + 8) * 65 + c + 1] = acc[mt][nt][3];
            }
        }
    }
    __syncthreads();

    // V transpose + split: [128 rows][64 h] -> g_Vt*[b][h][s/2], 16/thread.
    const int b  = row0 >> 11;
    const int s0 = row0 & 2047;
    #pragma unroll
    for (int i = 0; i < 16; i++) {
        int idx = tid + (i << 8);           // 0..4095
        int h  = idx & 63;
        int sp = idx >> 6;                  // local s-pair 0..63
        float v0 = vbuf[(2 * sp) * 65 + h];
        float v1 = vbuf[(2 * sp + 1) * 65 + h];
        uint32_t hi, lo;
        tsplit2(v0, v1, hi, lo);
        size_t o = (size_t)(b * 64 + h) * 1024 + (s0 >> 1) + sp;
        g_Vthp[o] = hi;
        g_Vtlp[o] = lo;
    }
}

// ---------------------------------------------------------------------------
// Kernel 2a: split-K flash attention partials. R13 loop structure with
// scalar LDS swapped for finest-grain ldmatrix.x2 (4 regs live, issue -20%).
// ---------------------------------------------------------------------------
#define KPITCH 72
#define SCL 0.18033688011112042f   /* 0.125 * log2(e) */

__global__ __launch_bounds__(128) void attn_part(float* __restrict__ dummy)
{
    __shared__ __align__(16) __nv_bfloat16 Kh[64 * KPITCH];
    __shared__ __align__(16) __nv_bfloat16 Kl[64 * KPITCH];
    __shared__ __align__(16) __nv_bfloat16 Vth[64 * KPITCH];
    __shared__ __align__(16) __nv_bfloat16 Vtl[64 * KPITCH];
    (void)dummy;

    const int tid = threadIdx.x;
    const int wm = tid >> 5;
    const int lane = tid & 31;
    const int grow = lane >> 2;
    const int tg = lane & 3;
    const int u = blockIdx.x;
    const int b = blockIdx.y;

    int qb, ci;
    if (u < 8)       { qb = u;                 ci = 0; }
    else if (u < 24) { qb = 8  + ((u - 8) >> 1);  ci = (u - 8) & 1; }
    else if (u < 48) { qb = 16 + (u - 24) / 3;    ci = (u - 24) % 3; }
    else             { qb = 24 + ((u - 48) >> 2); ci = (u - 48) & 3; }

    const int kb0 = ci * 8;
    const int kb1 = min(kb0 + 7, qb);

    const float* Qg = g_Q + (size_t)(b * SS + qb * 64 + wm * 16) * HH;

    uint32_t qh[4][4], ql[4][4];
    #pragma unroll
    for (int kt = 0; kt < 4; kt++) {
        float2 v00 = *(const float2*)(Qg + grow * HH + kt * 16 + tg * 2);
        float2 v10 = *(const float2*)(Qg + (grow + 8) * HH + kt * 16 + tg * 2);
        float2 v01 = *(const float2*)(Qg + grow * HH + kt * 16 + tg * 2 + 8);
        float2 v11 = *(const float2*)(Qg + (grow + 8) * HH + kt * 16 + tg * 2 + 8);
        tsplit2(v00.x, v00.y, qh[kt][0], ql[kt][0]);
        tsplit2(v10.x, v10.y, qh[kt][1], ql[kt][1]);
        tsplit2(v01.x, v01.y, qh[kt][2], ql[kt][2]);
        tsplit2(v11.x, v11.y, qh[kt][3], ql[kt][3]);
    }

    float o[8][4] = {};
    float m0 = -1e30f, m1 = -1e30f, l0 = 0.0f, l1 = 0.0f;
    const int qr0 = qb * 64 + wm * 16 + grow;

    const uint4* Khg4 = (const uint4*)(g_Khp + (size_t)b * SS * 32);
    const uint4* Klg4 = (const uint4*)(g_Klp + (size_t)b * SS * 32);
    const uint4* Vhg4 = (const uint4*)(g_Vthp + (size_t)b * 64 * 1024);
    const uint4* Vlg4 = (const uint4*)(g_Vtlp + (size_t)b * 64 * 1024);

    const uint32_t KhS = sptr(Kh), KlS = sptr(Kl);
    const uint32_t VhS = sptr(Vth), VlS = sptr(Vtl);
    // ldsm2 lane-row offset: lanes 0-7 -> matrix0 rows, 8-15 -> matrix1 (+16B).
    const uint32_t lrow2 = (lane & 7) * 144 + ((lane >> 3) & 1) * 16;

    for (int kb = kb0; kb <= kb1; kb++) {
        #pragma unroll
        for (int i = 0; i < 4; i++) {
            int idx = tid + (i << 7);
            int r = idx >> 3, q = idx & 7;
            *(uint4*)&Kh[r * KPITCH + q * 8]  = Khg4[(size_t)(kb * 64 + r) * 8 + q];
            *(uint4*)&Kl[r * KPITCH + q * 8]  = Klg4[(size_t)(kb * 64 + r) * 8 + q];
            *(uint4*)&Vth[r * KPITCH + q * 8] = Vhg4[(size_t)r * 256 + kb * 8 + q];
            *(uint4*)&Vtl[r * KPITCH + q * 8] = Vlg4[(size_t)r * 256 + kb * 8 + q];
        }
        __syncthreads();

        // ---- S = Q K^T (3-term split), ldsm2 per (nt, kt).
        float s[8][4] = {};
        #pragma unroll
        for (int nt = 0; nt < 8; nt++) {
            uint32_t base = (uint32_t)(nt * 8 * 144) + lrow2;
            #pragma unroll
            for (int kt = 0; kt < 4; kt++) {
                uint32_t bh0, bh1, bl0, bl1;
                ldsm2(bh0, bh1, KhS + base + kt * 32);
                ldsm2(bl0, bl1, KlS + base + kt * 32);
                mma_bf16(s[nt], qh[kt][0], qh[kt][1], qh[kt][2], qh[kt][3], bh0, bh1);
                mma_bf16(s[nt], qh[kt][0], qh[kt][1], qh[kt][2], qh[kt][3], bl0, bl1);
                mma_bf16(s[nt], ql[kt][0], ql[kt][1], ql[kt][2], ql[kt][3], bh0, bh1);
            }
        }

        if (kb == qb) {
            #pragma unroll
            for (int nt = 0; nt < 8; nt++) {
                int kc = kb * 64 + nt * 8 + tg * 2;
                s[nt][0] = (kc     > qr0)     ? -1e30f : s[nt][0] * SCL;
                s[nt][1] = (kc + 1 > qr0)     ? -1e30f : s[nt][1] * SCL;
                s[nt][2] = (kc     > qr0 + 8) ? -1e30f : s[nt][2] * SCL;
                s[nt][3] = (kc + 1 > qr0 + 8) ? -1e30f : s[nt][3] * SCL;
            }
        } else {
            #pragma unroll
            for (int nt = 0; nt < 8; nt++) {
                s[nt][0] *= SCL; s[nt][1] *= SCL;
                s[nt][2] *= SCL; s[nt][3] *= SCL;
            }
        }

        float mx0 = -1e30f, mx1 = -1e30f;
        #pragma unroll
        for (int nt = 0; nt < 8; nt++) {
            mx0 = fmaxf(mx0, fmaxf(s[nt][0], s[nt][1]));
            mx1 = fmaxf(mx1, fmaxf(s[nt][2], s[nt][3]));
        }
        mx0 = fmaxf(mx0, __shfl_xor_sync(0xffffffffu, mx0, 1));
        mx0 = fmaxf(mx0, __shfl_xor_sync(0xffffffffu, mx0, 2));
        mx1 = fmaxf(mx1, __shfl_xor_sync(0xffffffffu, mx1, 1));
        mx1 = fmaxf(mx1, __shfl_xor_sync(0xffffffffu, mx1, 2));
        float nm0 = fmaxf(m0, mx0), nm1 = fmaxf(m1, mx1);
        float a0 = exp2_fast(m0 - nm0), a1 = exp2_fast(m1 - nm1);
        m0 = nm0; m1 = nm1;

        float rs0 = 0.0f, rs1 = 0.0f;
        #pragma unroll
        for (int nt = 0; nt < 8; nt++) {
            float p0 = exp2_fast(s[nt][0] - nm0);
            float p1 = exp2_fast(s[nt][1] - nm0);
            float p2 = exp2_fast(s[nt][2] - nm1);
            float p3 = exp2_fast(s[nt][3] - nm1);
            s[nt][0] = p0; s[nt][1] = p1; s[nt][2] = p2; s[nt][3] = p3;
            rs0 += p0 + p1;
            rs1 += p2 + p3;
        }
        rs0 += __shfl_xor_sync(0xffffffffu, rs0, 1);
        rs0 += __shfl_xor_sync(0xffffffffu, rs0, 2);
        rs1 += __shfl_xor_sync(0xffffffffu, rs1, 1);
        rs1 += __shfl_xor_sync(0xffffffffu, rs1, 2);
        l0 = l0 * a0 + rs0;
        l1 = l1 * a1 + rs1;
        #pragma unroll
        for (int nt = 0; nt < 8; nt++) {
            o[nt][0] *= a0; o[nt][1] *= a0;
            o[nt][2] *= a1; o[nt][3] *= a1;
        }

        // ---- O += P V (3-term split), kt-outer (R13), ldsm2 V-frags.
        #pragma unroll
        for (int kt = 0; kt < 4; kt++) {
            uint32_t ph[4], pl[4];
            tsplit2(s[2 * kt][0],     s[2 * kt][1],     ph[0], pl[0]);
            tsplit2(s[2 * kt][2],     s[2 * kt][3],     ph[1], pl[1]);
            tsplit2(s[2 * kt + 1][0], s[2 * kt + 1][1], ph[2], pl[2]);
            tsplit2(s[2 * kt + 1][2], s[2 * kt + 1][3], ph[3], pl[3]);
            #pragma unroll
            for (int nt = 0; nt < 8; nt++) {
                uint32_t base = (uint32_t)(nt * 8 * 144) + lrow2 + kt * 32;
                uint32_t vh0, vh1, vl0, vl1;
                ldsm2(vh0, vh1, VhS + base);
                ldsm2(vl0, vl1, VlS + base);
                mma_bf16(o[nt], ph[0], ph[1], ph[2], ph[3], vh0, vh1);
                mma_bf16(o[nt], ph[0], ph[1], ph[2], ph[3], vl0, vl1);
                mma_bf16(o[nt], pl[0], pl[1], pl[2], pl[3], vh0, vh1);
            }
        }
        __syncthreads();
    }

    const size_t unit = ((size_t)b * 32 + qb) * 4 + ci;
    float* pO = g_pO + unit * 4096 + (size_t)(wm * 16) * 64;
    #pragma unroll
    for (int nt = 0; nt < 8; nt++) {
        *(float2*)(pO + grow * 64 + nt * 8 + tg * 2) = make_float2(o[nt][0], o[nt][1]);
        *(float2*)(pO + (grow + 8) * 64 + nt * 8 + tg * 2) = make_float2(o[nt][2], o[nt][3]);
    }
    if (tg == 0) {
        g_pm[unit * 64 + wm * 16 + grow]     = m0;
        g_pm[unit * 64 + wm * 16 + grow + 8] = m1;
        g_pl[unit * 64 + wm * 16 + grow]     = l0;
        g_pl[unit * 64 + wm * 16 + grow + 8] = l1;
    }
}

// ---------------------------------------------------------------------------
// Kernel 2b: combine attention partials.
// ---------------------------------------------------------------------------
__global__ __launch_bounds__(256) void attn_combine(float* __restrict__ Out)
{
    const int qb = blockIdx.x;
    const int b  = blockIdx.y;
    const int tid = threadIdx.x;
    const int r = tid >> 2;
    const int c0 = (tid & 3) * 16;
    const int nc = (qb >> 3) + 1;

    const size_t ubase = ((size_t)b * 32 + qb) * 4;

    float mi[4], li[4];
    float M = -1e30f;
    #pragma unroll 4
    for (int i = 0; i < nc; i++) {
        mi[i] = g_pm[(ubase + i) * 64 + r];
        li[i] = g_pl[(ubase + i) * 64 + r];
        M = fmaxf(M, mi[i]);
    }

    float acc[16] = {};
    float L = 0.0f;
    #pragma unroll 4
    for (int i = 0; i < nc; i++) {
        float al = exp2_fast(mi[i] - M);
        L += al * li[i];
        const float* pO = g_pO + (ubase + i) * 4096 + (size_t)r * 64 + c0;
        #pragma unroll
        for (int q = 0; q < 4; q++) {
            float4 v = *(const float4*)(pO + q * 4);
            acc[q * 4 + 0] += al * v.x;
            acc[q * 4 + 1] += al * v.y;
            acc[q * 4 + 2] += al * v.z;
            acc[q * 4 + 3] += al * v.w;
        }
    }

    float inv = 1.0f / L;
    float* Og = Out + (size_t)(b * SS + qb * 64 + r) * HH + c0;
    #pragma unroll
    for (int q = 0; q < 4; q++) {
        *(float4*)(Og + q * 4) = make_float4(acc[q * 4 + 0] * inv, acc[q * 4 + 1] * inv,
                                             acc[q * 4 + 2] * inv, acc[q * 4 + 3] * inv);
    }
}

// ---------------------------------------------------------------------------
extern "C" void kernel_launch(void* const* d_in, const int* in_sizes, int n_in,
                              void* d_out, int out_size)
{
    const float* x  = (const float*)d_in[0];
    const float* Wq = (const float*)d_in[1];
    const float* Wk = (const float*)d_in[2];
    const float* Wv = (const float*)d_in[3];
    float* out = (float*)d_out;
    (void)in_sizes; (void)n_in; (void)out_size;

    cudaFuncSetAttribute(qkv_mma, cudaFuncAttributeMaxDynamicSharedMemorySize,
                         QKV_SMEM);

    prep_w<<<768, 256>>>(Wq, Wk, Wv);
    qkv_mma<<<(BB * SS) / 128, 256, QKV_SMEM>>>(x);
    attn_part<<<dim3(80, BB), 128>>>(out);
    attn_combine<<<dim3(32, BB), 256>>>(out);
}